// round 3
// baseline (speedup 1.0000x reference)
#include <cuda_runtime.h>
#include <cuda_bf16.h>
#include <cstdint>
#include <cstddef>

// ---------------------------------------------------------------------------
// SCAEAttention via rank-64 factorization, heavy GEMMs on tensor cores
// (mma.sync m16n8k8 TF32, 3-pass hi/lo split for ~fp32 accuracy).
//
// Shapes: B=4, S=256, H=12, DH=64, D=768, FD=2048, FU=2048
//
//  E[h,k,f]   = sum_o W_O[h,k,o] * enc_W[f,o]                  [12,64,2048]
//  P[h,k,u]   = sum_i W_V[h,i,k] * up_dec_W[i,u]               [12,64,2048]
//  virtual[h,f,u] = mask[f,u] * sum_k E[h,k,f]*P[h,k,u]        [12,2048,2048]
//  t2[h,bs,k] = act_ln @ W_V[h]                                [12,1024,64]
//  S1[b,h,q,c]= probs[b,h] @ t2[h, b-rows]                     [4,12,256,64]
//  R[b,h,q,u] = probs[b,h] @ up_ln[b]                          [4,12,256,2048]
//  out[b,q,f] = sum_h ( S1[b,h] @ E[h]  +  R[b,h] @ virtual[h]^T )
//             + bias0[f] + inv[b,q]*g[f]
// ---------------------------------------------------------------------------

#define HN 12
#define DHN 64
#define DN 768
#define FDN 2048
#define FUN 2048
#define BSN 1024   // B*S

__device__ float g_E[HN * DHN * FDN];
__device__ float g_P[HN * DHN * FUN];
__device__ float g_virtual[HN * FDN * FUN];    // 201 MB
__device__ float g_t2[HN * BSN * DHN];
__device__ float g_S1[4 * HN * 256 * DHN];
__device__ float g_R[4 * HN * 256 * FUN];      // 100 MB
__device__ float g_actln[BSN * DN];
__device__ float g_upln[BSN * FUN];
__device__ float g_inv[BSN];
__device__ float g_v[HN * DHN];
__device__ float g_C[DN];
__device__ float g_gvec[FDN];
__device__ float g_bias0[FDN];

// ------------------------------- mma helpers -------------------------------
__device__ __forceinline__ void split_tf32(float x, uint32_t& hi, uint32_t& lo)
{
    asm("cvt.rna.tf32.f32 %0, %1;" : "=r"(hi) : "f"(x));
    float r = x - __uint_as_float(hi);
    asm("cvt.rna.tf32.f32 %0, %1;" : "=r"(lo) : "f"(r));
}

__device__ __forceinline__ void mma_tf32(float (&c)[4], const uint32_t (&a)[4],
                                         const uint32_t (&b)[2])
{
    asm volatile(
        "mma.sync.aligned.m16n8k8.row.col.f32.tf32.tf32.f32 "
        "{%0,%1,%2,%3}, {%4,%5,%6,%7}, {%8,%9}, {%0,%1,%2,%3};"
        : "+f"(c[0]), "+f"(c[1]), "+f"(c[2]), "+f"(c[3])
        : "r"(a[0]), "r"(a[1]), "r"(a[2]), "r"(a[3]), "r"(b[0]), "r"(b[1]));
}

// --------------------------- tf32x3 GEMM stage -----------------------------
// acc(m,n) += sum_k A(m,k)*B(k,n)
// TA: A(m,k) = A[k*lda + m] ; else A[m*lda + k]
// TB: B(k,n) = B[n*ldb + k] ; else B[k*ldb + n]
// 256 threads = WARPS_M x WARPS_N warps. Double-buffered smem, hi/lo planes.
template <int BM, int BN, bool TA, bool TB, int WARPS_M, int WARPS_N>
__device__ __forceinline__ void mma_stage(
    const float* __restrict__ A, int lda,
    const float* __restrict__ B, int ldb,
    int K, int tileM, int tileN,
    float (&acc)[BM / WARPS_M / 16][BN / WARPS_N / 8][4],
    uint32_t* As_h, uint32_t* As_l, uint32_t* Bs_h, uint32_t* Bs_l)
{
    constexpr int BK = 16, BKP = 20;
    constexpr int MT = BM / WARPS_M / 16;
    constexpr int NT = BN / WARPS_N / 8;
    constexpr int CA = BM * BK / 256;
    constexpr int CB = BN * BK / 256;

    const int tid = threadIdx.x;
    const int lane = tid & 31;
    const int warp = tid >> 5;
    const int g = lane >> 2, tc = lane & 3;
    const int wm = (warp % WARPS_M) * (BM / WARPS_M);
    const int wn = (warp / WARPS_M) * (BN / WARPS_N);

    float ra[CA], rb[CB];

    auto loadA = [&](int k0) {
#pragma unroll
        for (int r = 0; r < CA; r++) {
            int i = tid + r * 256;
            if (TA) { int k = i / BM, m = i - k * BM;
                      ra[r] = A[(size_t)(k0 + k) * lda + tileM + m]; }
            else    { int m = i / BK, k = i - m * BK;
                      ra[r] = A[(size_t)(tileM + m) * lda + k0 + k]; }
        }
    };
    auto loadB = [&](int k0) {
#pragma unroll
        for (int r = 0; r < CB; r++) {
            int i = tid + r * 256;
            if (TB) { int n = i / BK, k = i - n * BK;
                      rb[r] = B[(size_t)(tileN + n) * ldb + k0 + k]; }
            else    { int k = i / BN, n = i - k * BN;
                      rb[r] = B[(size_t)(k0 + k) * ldb + tileN + n]; }
        }
    };
    auto store = [&](int buf) {
        uint32_t* ah = As_h + buf * (BM * BKP);
        uint32_t* al = As_l + buf * (BM * BKP);
        uint32_t* bh = Bs_h + buf * (BN * BKP);
        uint32_t* bl = Bs_l + buf * (BN * BKP);
#pragma unroll
        for (int r = 0; r < CA; r++) {
            int i = tid + r * 256;
            int m, k;
            if (TA) { k = i / BM; m = i - k * BM; }
            else    { m = i / BK; k = i - m * BK; }
            uint32_t hi, lo; split_tf32(ra[r], hi, lo);
            ah[m * BKP + k] = hi; al[m * BKP + k] = lo;
        }
#pragma unroll
        for (int r = 0; r < CB; r++) {
            int i = tid + r * 256;
            int n, k;
            if (TB) { n = i / BK; k = i - n * BK; }
            else    { k = i / BN; n = i - k * BN; }
            uint32_t hi, lo; split_tf32(rb[r], hi, lo);
            bh[n * BKP + k] = hi; bl[n * BKP + k] = lo;
        }
    };
    auto compute = [&](int buf) {
        const uint32_t* ah = As_h + buf * (BM * BKP);
        const uint32_t* al = As_l + buf * (BM * BKP);
        const uint32_t* bh = Bs_h + buf * (BN * BKP);
        const uint32_t* bl = Bs_l + buf * (BN * BKP);
#pragma unroll
        for (int ks = 0; ks < BK; ks += 8) {
            uint32_t afh[MT][4], afl[MT][4], bfh[NT][2], bfl[NT][2];
#pragma unroll
            for (int i = 0; i < MT; i++) {
                int r0 = wm + i * 16 + g;
#pragma unroll
                for (int t = 0; t < 4; t++) {
                    int rr = r0 + (t & 1) * 8;
                    int cc = ks + tc + (t >> 1) * 4;
                    afh[i][t] = ah[rr * BKP + cc];
                    afl[i][t] = al[rr * BKP + cc];
                }
            }
#pragma unroll
            for (int j = 0; j < NT; j++) {
                int nr = wn + j * 8 + g;
                bfh[j][0] = bh[nr * BKP + ks + tc];
                bfh[j][1] = bh[nr * BKP + ks + tc + 4];
                bfl[j][0] = bl[nr * BKP + ks + tc];
                bfl[j][1] = bl[nr * BKP + ks + tc + 4];
            }
#pragma unroll
            for (int i = 0; i < MT; i++)
#pragma unroll
                for (int j = 0; j < NT; j++) {
                    mma_tf32(acc[i][j], afh[i], bfh[j]);
                    mma_tf32(acc[i][j], afh[i], bfl[j]);
                    mma_tf32(acc[i][j], afl[i], bfh[j]);
                }
        }
    };

    int niter = K / BK;
    loadA(0); loadB(0);
    store(0);
    __syncthreads();
    for (int it = 0; it < niter; ++it) {
        if (it + 1 < niter) { loadA((it + 1) * BK); loadB((it + 1) * BK); }
        compute(it & 1);
        if (it + 1 < niter) store((it + 1) & 1);
        __syncthreads();
    }
}

// --------------------------- generic mma GEMM ------------------------------
template <int BM, int BN, bool TA, bool TB, int WARPS_M, int WARPS_N>
__global__ void __launch_bounds__(256, 1) mma_gemm(
    const float* __restrict__ A, int lda, long sAo, long sAi,
    const float* __restrict__ B, int ldb, long sBo, long sBi,
    float* __restrict__ C, int ldc, long sCo, long sCi,
    int K, int bsplit,
    const int* __restrict__ mask, int mld)
{
    constexpr int BKP = 20;
    constexpr int MT = BM / WARPS_M / 16;
    constexpr int NT = BN / WARPS_N / 8;

    extern __shared__ uint32_t sm[];
    uint32_t* As_h = sm;
    uint32_t* As_l = As_h + 2 * BM * BKP;
    uint32_t* Bs_h = As_l + 2 * BM * BKP;
    uint32_t* Bs_l = Bs_h + 2 * BN * BKP;

    int bz = blockIdx.z;
    int bo = bz / bsplit, bi = bz - bo * bsplit;
    A += bo * sAo + bi * sAi;
    B += bo * sBo + bi * sBi;
    C += bo * sCo + bi * sCi;

    const int tileM = blockIdx.y * BM;
    const int tileN = blockIdx.x * BN;

    float acc[MT][NT][4] = {};
    mma_stage<BM, BN, TA, TB, WARPS_M, WARPS_N>(A, lda, B, ldb, K, tileM, tileN,
                                                acc, As_h, As_l, Bs_h, Bs_l);

    const int lane = threadIdx.x & 31, warp = threadIdx.x >> 5;
    const int g = lane >> 2, tc = lane & 3;
    const int wm = (warp % WARPS_M) * (BM / WARPS_M);
    const int wn = (warp / WARPS_M) * (BN / WARPS_N);

#pragma unroll
    for (int i = 0; i < MT; i++) {
        int m0 = tileM + wm + i * 16 + g;
#pragma unroll
        for (int j = 0; j < NT; j++) {
            int n0 = tileN + wn + j * 8 + 2 * tc;
            if (mask != nullptr) {
                C[(size_t)m0 * ldc + n0]     = acc[i][j][0] * (float)mask[(size_t)m0 * mld + n0];
                C[(size_t)m0 * ldc + n0 + 1] = acc[i][j][1] * (float)mask[(size_t)m0 * mld + n0 + 1];
                C[(size_t)(m0 + 8) * ldc + n0]     = acc[i][j][2] * (float)mask[(size_t)(m0 + 8) * mld + n0];
                C[(size_t)(m0 + 8) * ldc + n0 + 1] = acc[i][j][3] * (float)mask[(size_t)(m0 + 8) * mld + n0 + 1];
            } else {
                C[(size_t)m0 * ldc + n0]     = acc[i][j][0];
                C[(size_t)m0 * ldc + n0 + 1] = acc[i][j][1];
                C[(size_t)(m0 + 8) * ldc + n0]     = acc[i][j][2];
                C[(size_t)(m0 + 8) * ldc + n0 + 1] = acc[i][j][3];
            }
        }
    }
}

// --------------------------- final fused kernel ----------------------------
// out[b,q,f] = sum_h (S1[b,h]@E[h] (K=64) + R[b,h]@virtual[h]^T (K=2048))
//            + bias0[f] + inv[b,q]*g[f]
__global__ void __launch_bounds__(256, 1) final_kernel(float* __restrict__ out)
{
    constexpr int BM = 128, BN = 128, WARPS_M = 2, WARPS_N = 4;
    constexpr int BKP = 20;
    constexpr int MT = BM / WARPS_M / 16;   // 4
    constexpr int NT = BN / WARPS_N / 8;    // 4

    extern __shared__ uint32_t sm[];
    uint32_t* As_h = sm;
    uint32_t* As_l = As_h + 2 * BM * BKP;
    uint32_t* Bs_h = As_l + 2 * BM * BKP;
    uint32_t* Bs_l = Bs_h + 2 * BN * BKP;

    const int b = blockIdx.z;
    const int tileM = blockIdx.y * BM;     // q within this batch's 256
    const int tileN = blockIdx.x * BN;     // f

    float acc[MT][NT][4] = {};

    for (int h = 0; h < HN; ++h) {
        const float* A1 = g_S1 + ((size_t)(b * HN + h)) * 256 * DHN;
        const float* B1 = g_E + (size_t)h * DHN * FDN;
        mma_stage<BM, BN, false, false, WARPS_M, WARPS_N>(
            A1, DHN, B1, FDN, DHN, tileM, tileN, acc, As_h, As_l, Bs_h, Bs_l);

        const float* A2 = g_R + ((size_t)(b * HN + h)) * 256 * FUN;
        const float* B2 = g_virtual + (size_t)h * FDN * FUN;
        mma_stage<BM, BN, false, true, WARPS_M, WARPS_N>(
            A2, FUN, B2, FUN, FUN, tileM, tileN, acc, As_h, As_l, Bs_h, Bs_l);
    }

    const int lane = threadIdx.x & 31, warp = threadIdx.x >> 5;
    const int g = lane >> 2, tc = lane & 3;
    const int wm = (warp % WARPS_M) * (BM / WARPS_M);
    const int wn = (warp / WARPS_M) * (BN / WARPS_N);

#pragma unroll
    for (int i = 0; i < MT; i++) {
        int q0 = tileM + wm + i * 16 + g;
        float inv0 = g_inv[b * 256 + q0];
        float inv1 = g_inv[b * 256 + q0 + 8];
#pragma unroll
        for (int j = 0; j < NT; j++) {
            int f0 = tileN + wn + j * 8 + 2 * tc;
            float bA = g_bias0[f0], bB = g_bias0[f0 + 1];
            float gA = g_gvec[f0],  gB = g_gvec[f0 + 1];
            out[((size_t)b * 256 + q0) * FDN + f0]           = acc[i][j][0] + bA + inv0 * gA;
            out[((size_t)b * 256 + q0) * FDN + f0 + 1]       = acc[i][j][1] + bB + inv0 * gB;
            out[((size_t)b * 256 + q0 + 8) * FDN + f0]       = acc[i][j][2] + bA + inv1 * gA;
            out[((size_t)b * 256 + q0 + 8) * FDN + f0 + 1]   = acc[i][j][3] + bB + inv1 * gB;
        }
    }
}

// --------------------------- small kernels ---------------------------------
__global__ void prep_kernel(const float* __restrict__ resid,
                            const float* __restrict__ ln,
                            const float* __restrict__ pruned)
{
    int row = blockIdx.x;
    float inv = 1.0f / ln[row];
    if (threadIdx.x == 0) g_inv[row] = inv;
    for (int d = threadIdx.x; d < DN; d += blockDim.x)
        g_actln[(size_t)row * DN + d] = resid[(size_t)row * DN + d] * inv;
    for (int u = threadIdx.x; u < FUN; u += blockDim.x)
        g_upln[(size_t)row * FUN + u] = pruned[(size_t)row * FUN + u] * inv;
}

__global__ void bias_v_kernel(const float* __restrict__ W_V,
                              const float* __restrict__ up_b_dec)
{
    int hk = blockIdx.x * blockDim.x + threadIdx.x;
    if (hk >= HN * DHN) return;
    int h = hk >> 6, k = hk & 63;
    const float* base = W_V + (size_t)h * DN * DHN + k;
    float s = 0.f;
    for (int m = 0; m < DN; m++) s = fmaf(base[(size_t)m * DHN], up_b_dec[m], s);
    g_v[hk] = s;
}

__global__ void bias_C_kernel(const float* __restrict__ W_O)
{
    int d = blockIdx.x * blockDim.x + threadIdx.x;
    if (d >= DN) return;
    float s = 0.f;
    for (int hk = 0; hk < HN * DHN; hk++)
        s = fmaf(g_v[hk], W_O[(size_t)hk * DN + d], s);
    g_C[d] = s;
}

// warp-per-f: coalesced enc_W row reads + shfl reduction
__global__ void bias_g_kernel(const float* __restrict__ enc_W,
                              const float* __restrict__ enc_b,
                              const float* __restrict__ b_dec)
{
    int w = (blockIdx.x * blockDim.x + threadIdx.x) >> 5;
    int lane = threadIdx.x & 31;
    if (w >= FDN) return;
    const float* row = enc_W + (size_t)w * DN;
    float sg = 0.f, sb = 0.f;
    for (int d = lane; d < DN; d += 32) {
        float r = row[d];
        sg = fmaf(r, g_C[d], sg);
        sb = fmaf(r, b_dec[d], sb);
    }
#pragma unroll
    for (int o = 16; o; o >>= 1) {
        sg += __shfl_xor_sync(0xffffffffu, sg, o);
        sb += __shfl_xor_sync(0xffffffffu, sb, o);
    }
    if (lane == 0) { g_gvec[w] = sg; g_bias0[w] = enc_b[w] - sb; }
}

// --------------------------- launch ----------------------------------------
static inline int smem_bytes(int BM, int BN) { return 16 * 20 * (BM + BN); }

extern "C" void kernel_launch(void* const* d_in, const int* in_sizes, int n_in,
                              void* d_out, int out_size)
{
    (void)in_sizes; (void)n_in; (void)out_size;
    const float* resid    = (const float*)d_in[0];
    const float* ln       = (const float*)d_in[1];
    const float* probs    = (const float*)d_in[2];
    const float* W_O      = (const float*)d_in[3];
    const float* W_V      = (const float*)d_in[4];
    const float* enc_W    = (const float*)d_in[5];
    const float* enc_b    = (const float*)d_in[6];
    const float* b_dec    = (const float*)d_in[7];
    const float* up_dec_W = (const float*)d_in[8];
    const float* up_b_dec = (const float*)d_in[9];
    const float* pruned   = (const float*)d_in[10];
    const int*   cmask    = (const int*)d_in[11];
    float* out = (float*)d_out;

    float *pE, *pP, *pT2, *pV, *pS1, *pR, *pAct, *pUp;
    cudaGetSymbolAddress((void**)&pE,  g_E);
    cudaGetSymbolAddress((void**)&pP,  g_P);
    cudaGetSymbolAddress((void**)&pT2, g_t2);
    cudaGetSymbolAddress((void**)&pV,  g_virtual);
    cudaGetSymbolAddress((void**)&pS1, g_S1);
    cudaGetSymbolAddress((void**)&pR,  g_R);
    cudaGetSymbolAddress((void**)&pAct, g_actln);
    cudaGetSymbolAddress((void**)&pUp,  g_upln);

    // opt-in dynamic smem (> 48KB) for all mma kernels
    cudaFuncSetAttribute((const void*)mma_gemm<64,128,false,true,2,4>,
                         cudaFuncAttributeMaxDynamicSharedMemorySize, smem_bytes(64,128));
    cudaFuncSetAttribute((const void*)mma_gemm<64,128,true,false,2,4>,
                         cudaFuncAttributeMaxDynamicSharedMemorySize, smem_bytes(64,128));
    cudaFuncSetAttribute((const void*)mma_gemm<128,64,false,false,4,2>,
                         cudaFuncAttributeMaxDynamicSharedMemorySize, smem_bytes(128,64));
    cudaFuncSetAttribute((const void*)mma_gemm<128,128,true,false,2,4>,
                         cudaFuncAttributeMaxDynamicSharedMemorySize, smem_bytes(128,128));
    cudaFuncSetAttribute((const void*)mma_gemm<128,128,false,false,2,4>,
                         cudaFuncAttributeMaxDynamicSharedMemorySize, smem_bytes(128,128));
    cudaFuncSetAttribute((const void*)final_kernel,
                         cudaFuncAttributeMaxDynamicSharedMemorySize, smem_bytes(128,128));

    // elementwise prep + rank-1 bias chain
    prep_kernel<<<BSN, 256>>>(resid, ln, pruned);
    bias_v_kernel<<<3, 256>>>(W_V, up_b_dec);
    bias_C_kernel<<<3, 256>>>(W_O);
    bias_g_kernel<<<FDN * 32 / 256, 256>>>(enc_W, enc_b, b_dec);

    // E[h] = W_O[h] @ enc_W^T : M=64,N=2048,K=768 (NT)
    mma_gemm<64,128,false,true,2,4><<<dim3(16,1,HN), 256, smem_bytes(64,128)>>>(
        W_O, DN, (long)DHN*DN, 0,
        enc_W, DN, 0, 0,
        pE, FDN, (long)DHN*FDN, 0,
        DN, 1, nullptr, 0);

    // P[h] = W_V[h]^T @ up_dec_W : M=64,N=2048,K=768 (TN)
    mma_gemm<64,128,true,false,2,4><<<dim3(16,1,HN), 256, smem_bytes(64,128)>>>(
        W_V, DHN, (long)DN*DHN, 0,
        up_dec_W, FUN, 0, 0,
        pP, FUN, (long)DHN*FUN, 0,
        DN, 1, nullptr, 0);

    // t2[h] = act_ln @ W_V[h] : M=1024,N=64,K=768 (NN)
    mma_gemm<128,64,false,false,4,2><<<dim3(1,8,HN), 256, smem_bytes(128,64)>>>(
        pAct, DN, 0, 0,
        W_V, DHN, (long)DN*DHN, 0,
        pT2, DHN, (long)BSN*DHN, 0,
        DN, 1, nullptr, 0);

    // virtual[h] = mask .* (E[h]^T @ P[h]) : M=2048,N=2048,K=64 (TN) + mask
    mma_gemm<128,128,true,false,2,4><<<dim3(16,16,HN), 256, smem_bytes(128,128)>>>(
        pE, FDN, (long)DHN*FDN, 0,
        pP, FUN, (long)DHN*FUN, 0,
        pV, FUN, (long)FDN*FUN, 0,
        DHN, 1, cmask, FUN);

    // S1[b,h] = probs[b,h] @ t2[h, b-rows] : M=256,N=64,K=256 (NN)
    mma_gemm<128,64,false,false,4,2><<<dim3(1,2,4*HN), 256, smem_bytes(128,64)>>>(
        probs, 256, (long)HN*256*256, (long)256*256,
        pT2, DHN, (long)256*DHN, (long)BSN*DHN,
        pS1, DHN, (long)HN*256*DHN, (long)256*DHN,
        256, HN, nullptr, 0);

    // R[b,h] = probs[b,h] @ up_ln[b] : M=256,N=2048,K=256 (NN)
    mma_gemm<128,128,false,false,2,4><<<dim3(16,2,4*HN), 256, smem_bytes(128,128)>>>(
        probs, 256, (long)HN*256*256, (long)256*256,
        pUp, FUN, (long)256*FUN, 0,
        pR, FUN, (long)HN*256*FUN, (long)256*FUN,
        256, HN, nullptr, 0);

    // out = sum_h (S1@E + R@virtual^T) + bias
    final_kernel<<<dim3(16,2,4), 256, smem_bytes(128,128)>>>(out);
}

// round 8
// speedup vs baseline: 2.3747x; 2.3747x over previous
#include <cuda_runtime.h>
#include <cuda_fp16.h>
#include <cstdint>
#include <cstddef>

// ---------------------------------------------------------------------------
// SCAEAttention via rank-64 factorization; all GEMMs on legacy mma.sync
// m16n8k16 fp16 with 3-pass hi/lo split (scaled residual => ~22-bit mantissa).
//
// Shapes: B=4, S=256, H=12, DH=64, D=768, FD=2048, FU=2048
//
//  E[hk,f]    = sum_o W_O[hk,o] * enc_W[f,o]          (M=768,N=2048,K=768)
//  P[hk,u]    = sum_i W_V[h,i,k] * up_dec_W[i,u]      (M=768,N=2048,K=768)
//  virtual[h] = mask .* (E[h]^T @ P[h])               (M=2048,N=2048,K=64)x12
//  t2[h]      = act_ln @ W_V[h]                       (M=1024,N=64,K=768)x12
//  S1[b,h]    = probs[b,h] @ t2[h,b-rows]             (M=256,N=64,K=256)x48
//  R[b,h]     = probs[b,h] @ up_ln[b]                 (M=256,N=2048,K=256)x48
//  out[b,q,f] = sum_h (S1[b,h]@E[h] + R[b,h]@virtual[h]^T) + bias0 + inv*g
// ---------------------------------------------------------------------------

#define HN 12
#define DHN 64
#define DN 768
#define FDN 2048
#define FUN 2048
#define BSN 1024

__device__ float g_E[HN * DHN * FDN];
__device__ float g_P[HN * DHN * FUN];
__device__ float g_virtual[HN * FDN * FUN];
__device__ float g_t2[HN * BSN * DHN];
__device__ float g_S1[4 * HN * 256 * DHN];
__device__ float g_R[4 * HN * 256 * FUN];
__device__ float g_actln[BSN * DN];
__device__ float g_upln[BSN * FUN];
__device__ float g_inv[BSN];
__device__ float g_v[HN * DHN];
__device__ float g_C[DN];
__device__ float g_gvec[FDN];
__device__ float g_bias0[FDN];

#define LO_SCALE 2048.0f
#define LO_INV   (1.0f / 2048.0f)
#define STRD 40   // halves per smem row (32 + 8 pad): conflict-free frag reads

// ------------------------------- mma helper --------------------------------
__device__ __forceinline__ void mma_f16(float (&c)[4], const uint32_t (&a)[4],
                                        const uint32_t (&b)[2])
{
    asm volatile(
        "mma.sync.aligned.m16n8k16.row.col.f32.f16.f16.f32 "
        "{%0,%1,%2,%3}, {%4,%5,%6,%7}, {%8,%9}, {%0,%1,%2,%3};"
        : "+f"(c[0]), "+f"(c[1]), "+f"(c[2]), "+f"(c[3])
        : "r"(a[0]), "r"(a[1]), "r"(a[2]), "r"(a[3]), "r"(b[0]), "r"(b[1]));
}

__device__ __forceinline__ void split_pack(float x, float y,
                                           uint32_t& hi2, uint32_t& lo2)
{
    __half hx = __float2half_rn(x), hy = __float2half_rn(y);
    float rx = (x - __half2float(hx)) * LO_SCALE;
    float ry = (y - __half2float(hy)) * LO_SCALE;
    __half lx = __float2half_rn(rx), ly = __float2half_rn(ry);
    hi2 = ((uint32_t)__half_as_ushort(hy) << 16) | __half_as_ushort(hx);
    lo2 = ((uint32_t)__half_as_ushort(ly) << 16) | __half_as_ushort(lx);
}

// ------------------------ staging: gmem -> regs -> smem --------------------
// MODE 0: X[m*ld + k]  (k-fast mapping, float2 coalesced)
// MODE 1: X[k*ld + m]  (m-fast mapping, coalesced across m)
// MODE 2: W_V pack: X[(m>>6)*(DN*DHN) + k*DHN + (m&63)] (m-fast)
template <int ROWS, int MODE>
__device__ __forceinline__ void ld_tile(const float* __restrict__ X, int ld,
                                        int k0, int row0, float2* r)
{
    constexpr int IT = ROWS * 16 / 256;
#pragma unroll
    for (int t = 0; t < IT; t++) {
        int p = threadIdx.x + t * 256;
        int m, kp;
        if (MODE == 0) { m = p >> 4; kp = (p & 15) * 2; }
        else           { m = p & (ROWS - 1); kp = (p / ROWS) * 2; }
        if (MODE == 0) {
            r[t] = *(const float2*)&X[(size_t)(row0 + m) * ld + k0 + kp];
        } else if (MODE == 1) {
            r[t].x = X[(size_t)(k0 + kp) * ld + row0 + m];
            r[t].y = X[(size_t)(k0 + kp + 1) * ld + row0 + m];
        } else {
            int mm = row0 + m;
            const float* bb = X + (size_t)(mm >> 6) * (DN * DHN) + (mm & 63);
            r[t].x = bb[(size_t)(k0 + kp) * DHN];
            r[t].y = bb[(size_t)(k0 + kp + 1) * DHN];
        }
    }
}

template <int ROWS, int MODE>
__device__ __forceinline__ void st_tile(const float2* r, __half* hp, __half* lp)
{
    constexpr int IT = ROWS * 16 / 256;
#pragma unroll
    for (int t = 0; t < IT; t++) {
        int p = threadIdx.x + t * 256;
        int m, kp;
        if (MODE == 0) { m = p >> 4; kp = (p & 15) * 2; }
        else           { m = p & (ROWS - 1); kp = (p / ROWS) * 2; }
        uint32_t h2, l2;
        split_pack(r[t].x, r[t].y, h2, l2);
        int off = m * STRD + kp;
        *(uint32_t*)(hp + off) = h2;
        *(uint32_t*)(lp + off) = l2;
    }
}

// --------------------------- fp16x3 GEMM stage -----------------------------
// acc += A(128 x K) * B(K x BN); 8 warps = WM x (8/WM).
// hh: hi*hi accum ; ml: (hi*lo_s + lo_s*hi) accum, combined hh + ml/2048.
template <int BN, int AMODE, int BMODE, int WM>
__device__ __forceinline__ void mma_stage(
    const float* __restrict__ A, int lda,
    const float* __restrict__ B, int ldb,
    int K, int tileM, int tileN,
    float (&hh)[8 / WM][BN * WM / 64][4],
    float (&ml)[8 / WM][BN * WM / 64][4],
    __half* sm)
{
    constexpr int WN = 8 / WM;
    constexpr int MT = 8 / WM;
    constexpr int NT = BN * WM / 64;
    constexpr int APL = 128 * STRD;
    constexpr int BPL = BN * STRD;
    constexpr int BUF = 2 * APL + 2 * BPL;

    const int lane = threadIdx.x & 31, warp = threadIdx.x >> 5;
    const int g = lane >> 2, tc = lane & 3;
    const int wm = (warp % WM) * (128 / WM);
    const int wn = (warp / WM) * (BN / WN);

    float2 ra[8], rb[BN / 16];

    auto stor = [&](int buf) {
        __half* base = sm + buf * BUF;
        st_tile<128, AMODE>(ra, base, base + APL);
        st_tile<BN, BMODE>(rb, base + 2 * APL, base + 2 * APL + BPL);
    };
    auto comp = [&](int buf) {
        __half* base = sm + buf * BUF;
        const __half* Ah = base;
        const __half* Al = base + APL;
        const __half* Bh = base + 2 * APL;
        const __half* Bl = base + 2 * APL + BPL;
#pragma unroll
        for (int ks = 0; ks < 32; ks += 16) {
            uint32_t afh[MT][4], afl[MT][4], bfh[NT][2], bfl[NT][2];
            const int c0 = ks + 2 * tc;
#pragma unroll
            for (int i = 0; i < MT; i++) {
                int r0 = wm + i * 16 + g;
                afh[i][0] = *(const uint32_t*)(Ah + r0 * STRD + c0);
                afh[i][1] = *(const uint32_t*)(Ah + (r0 + 8) * STRD + c0);
                afh[i][2] = *(const uint32_t*)(Ah + r0 * STRD + c0 + 8);
                afh[i][3] = *(const uint32_t*)(Ah + (r0 + 8) * STRD + c0 + 8);
                afl[i][0] = *(const uint32_t*)(Al + r0 * STRD + c0);
                afl[i][1] = *(const uint32_t*)(Al + (r0 + 8) * STRD + c0);
                afl[i][2] = *(const uint32_t*)(Al + r0 * STRD + c0 + 8);
                afl[i][3] = *(const uint32_t*)(Al + (r0 + 8) * STRD + c0 + 8);
            }
#pragma unroll
            for (int j = 0; j < NT; j++) {
                int n0 = wn + j * 8 + g;
                bfh[j][0] = *(const uint32_t*)(Bh + n0 * STRD + c0);
                bfh[j][1] = *(const uint32_t*)(Bh + n0 * STRD + c0 + 8);
                bfl[j][0] = *(const uint32_t*)(Bl + n0 * STRD + c0);
                bfl[j][1] = *(const uint32_t*)(Bl + n0 * STRD + c0 + 8);
            }
#pragma unroll
            for (int i = 0; i < MT; i++)
#pragma unroll
                for (int j = 0; j < NT; j++) {
                    mma_f16(hh[i][j], afh[i], bfh[j]);
                    mma_f16(ml[i][j], afh[i], bfl[j]);
                    mma_f16(ml[i][j], afl[i], bfh[j]);
                }
        }
    };

    const int niter = K / 32;
    ld_tile<128, AMODE>(A, lda, 0, tileM, ra);
    ld_tile<BN, BMODE>(B, ldb, 0, tileN, rb);
    stor(0);
    __syncthreads();
    for (int it = 0; it < niter; it++) {
        if (it + 1 < niter) {
            ld_tile<128, AMODE>(A, lda, (it + 1) * 32, tileM, ra);
            ld_tile<BN, BMODE>(B, ldb, (it + 1) * 32, tileN, rb);
        }
        comp(it & 1);
        if (it + 1 < niter) stor((it + 1) & 1);
        __syncthreads();
    }
}

// --------------------------- generic mma GEMM ------------------------------
template <int BN, int AMODE, int BMODE, bool MASK_, int WM>
__global__ void __launch_bounds__(256, 1) mma_gemm(
    const float* __restrict__ A, int lda, long sAo, long sAi,
    const float* __restrict__ B, int ldb, long sBo, long sBi,
    float* __restrict__ C, int ldc, long sCo, long sCi,
    int K, int bsplit,
    const int* __restrict__ mask, int mld)
{
    constexpr int MT = 8 / WM;
    constexpr int NT = BN * WM / 64;
    extern __shared__ __half sm[];

    const int bz = blockIdx.z;
    const int bo = bz / bsplit, bi = bz - bo * bsplit;
    A += bo * sAo + bi * sAi;
    B += bo * sBo + bi * sBi;
    C += bo * sCo + bi * sCi;
    const int tileM = blockIdx.y * 128;
    const int tileN = blockIdx.x * BN;

    float hh[MT][NT][4] = {};
    float ml[MT][NT][4] = {};
    mma_stage<BN, AMODE, BMODE, WM>(A, lda, B, ldb, K, tileM, tileN, hh, ml, sm);

    const int lane = threadIdx.x & 31, warp = threadIdx.x >> 5;
    const int g = lane >> 2, tc = lane & 3;
    const int wm = (warp % WM) * (128 / WM);
    const int wn = (warp / WM) * (BN / (8 / WM));

#pragma unroll
    for (int i = 0; i < MT; i++) {
        int m0 = tileM + wm + i * 16 + g;
#pragma unroll
        for (int j = 0; j < NT; j++) {
            int n0 = tileN + wn + j * 8 + 2 * tc;
            float v0 = hh[i][j][0] + ml[i][j][0] * LO_INV;
            float v1 = hh[i][j][1] + ml[i][j][1] * LO_INV;
            float v2 = hh[i][j][2] + ml[i][j][2] * LO_INV;
            float v3 = hh[i][j][3] + ml[i][j][3] * LO_INV;
            if (MASK_) {
                v0 *= (float)mask[(size_t)m0 * mld + n0];
                v1 *= (float)mask[(size_t)m0 * mld + n0 + 1];
                v2 *= (float)mask[(size_t)(m0 + 8) * mld + n0];
                v3 *= (float)mask[(size_t)(m0 + 8) * mld + n0 + 1];
            }
            C[(size_t)m0 * ldc + n0]           = v0;
            C[(size_t)m0 * ldc + n0 + 1]       = v1;
            C[(size_t)(m0 + 8) * ldc + n0]     = v2;
            C[(size_t)(m0 + 8) * ldc + n0 + 1] = v3;
        }
    }
}

// --------------------------- final fused kernel ----------------------------
// out[b,q,f] = sum_h (S1[b,h]@E[h] (K=64) + R[b,h]@virtual[h]^T (K=2048)) + bias
__global__ void __launch_bounds__(256, 1) final_kernel(float* __restrict__ out)
{
    constexpr int WM = 2, MT = 4, NT = 4;
    extern __shared__ __half sm[];

    const int b = blockIdx.z;
    const int tileM = blockIdx.y * 128;
    const int tileN = blockIdx.x * 128;

    float hh[MT][NT][4] = {};
    float ml[MT][NT][4] = {};

    for (int h = 0; h < HN; ++h) {
        const float* A1 = g_S1 + ((size_t)(b * HN + h)) * 256 * DHN;
        const float* B1 = g_E + (size_t)h * DHN * FDN;        // B(n=f,k=c): k-major
        mma_stage<128, 0, 1, WM>(A1, DHN, B1, FDN, DHN, tileM, tileN, hh, ml, sm);

        const float* A2 = g_R + ((size_t)(b * HN + h)) * 256 * FUN;
        const float* B2 = g_virtual + (size_t)h * FDN * FUN;  // B(n=f,k=u): n-major
        mma_stage<128, 0, 0, WM>(A2, FUN, B2, FUN, FUN, tileM, tileN, hh, ml, sm);
    }

    const int lane = threadIdx.x & 31, warp = threadIdx.x >> 5;
    const int g = lane >> 2, tc = lane & 3;
    const int wm = (warp % WM) * 64;
    const int wn = (warp / WM) * 32;

#pragma unroll
    for (int i = 0; i < MT; i++) {
        int q0 = tileM + wm + i * 16 + g;
        float inv0 = g_inv[b * 256 + q0];
        float inv1 = g_inv[b * 256 + q0 + 8];
#pragma unroll
        for (int j = 0; j < NT; j++) {
            int f0 = tileN + wn + j * 8 + 2 * tc;
            float bA = g_bias0[f0], bB = g_bias0[f0 + 1];
            float gA = g_gvec[f0],  gB = g_gvec[f0 + 1];
            out[((size_t)b * 256 + q0) * FDN + f0] =
                hh[i][j][0] + ml[i][j][0] * LO_INV + bA + inv0 * gA;
            out[((size_t)b * 256 + q0) * FDN + f0 + 1] =
                hh[i][j][1] + ml[i][j][1] * LO_INV + bB + inv0 * gB;
            out[((size_t)b * 256 + q0 + 8) * FDN + f0] =
                hh[i][j][2] + ml[i][j][2] * LO_INV + bA + inv1 * gA;
            out[((size_t)b * 256 + q0 + 8) * FDN + f0 + 1] =
                hh[i][j][3] + ml[i][j][3] * LO_INV + bB + inv1 * gB;
        }
    }
}

// --------------------------- small kernels ---------------------------------
__global__ void prep_kernel(const float* __restrict__ resid,
                            const float* __restrict__ ln,
                            const float* __restrict__ pruned)
{
    int row = blockIdx.x;
    float inv = 1.0f / ln[row];
    if (threadIdx.x == 0) g_inv[row] = inv;
    for (int d = threadIdx.x; d < DN; d += blockDim.x)
        g_actln[(size_t)row * DN + d] = resid[(size_t)row * DN + d] * inv;
    for (int u = threadIdx.x; u < FUN; u += blockDim.x)
        g_upln[(size_t)row * FUN + u] = pruned[(size_t)row * FUN + u] * inv;
}

__global__ void bias_v_kernel(const float* __restrict__ W_V,
                              const float* __restrict__ up_b_dec)
{
    int hk = blockIdx.x * blockDim.x + threadIdx.x;
    if (hk >= HN * DHN) return;
    int h = hk >> 6, k = hk & 63;
    const float* base = W_V + (size_t)h * DN * DHN + k;
    float s = 0.f;
    for (int m = 0; m < DN; m++) s = fmaf(base[(size_t)m * DHN], up_b_dec[m], s);
    g_v[hk] = s;
}

__global__ void bias_C_kernel(const float* __restrict__ W_O)
{
    int d = blockIdx.x * blockDim.x + threadIdx.x;
    if (d >= DN) return;
    float s = 0.f;
    for (int hk = 0; hk < HN * DHN; hk++)
        s = fmaf(g_v[hk], W_O[(size_t)hk * DN + d], s);
    g_C[d] = s;
}

__global__ void bias_g_kernel(const float* __restrict__ enc_W,
                              const float* __restrict__ enc_b,
                              const float* __restrict__ b_dec)
{
    int w = (blockIdx.x * blockDim.x + threadIdx.x) >> 5;
    int lane = threadIdx.x & 31;
    if (w >= FDN) return;
    const float* row = enc_W + (size_t)w * DN;
    float sg = 0.f, sb = 0.f;
    for (int d = lane; d < DN; d += 32) {
        float r = row[d];
        sg = fmaf(r, g_C[d], sg);
        sb = fmaf(r, b_dec[d], sb);
    }
#pragma unroll
    for (int o = 16; o; o >>= 1) {
        sg += __shfl_xor_sync(0xffffffffu, sg, o);
        sb += __shfl_xor_sync(0xffffffffu, sb, o);
    }
    if (lane == 0) { g_gvec[w] = sg; g_bias0[w] = enc_b[w] - sb; }
}

// --------------------------- launch ----------------------------------------
static constexpr int SMB128 = 2 * (2 * 128 * STRD + 2 * 128 * STRD) * 2; // 81920
static constexpr int SMB64  = 2 * (2 * 128 * STRD + 2 * 64 * STRD) * 2;  // 61440

extern "C" void kernel_launch(void* const* d_in, const int* in_sizes, int n_in,
                              void* d_out, int out_size)
{
    (void)in_sizes; (void)n_in; (void)out_size;
    const float* resid    = (const float*)d_in[0];
    const float* ln       = (const float*)d_in[1];
    const float* probs    = (const float*)d_in[2];
    const float* W_O      = (const float*)d_in[3];
    const float* W_V      = (const float*)d_in[4];
    const float* enc_W    = (const float*)d_in[5];
    const float* enc_b    = (const float*)d_in[6];
    const float* b_dec    = (const float*)d_in[7];
    const float* up_dec_W = (const float*)d_in[8];
    const float* up_b_dec = (const float*)d_in[9];
    const float* pruned   = (const float*)d_in[10];
    const int*   cmask    = (const int*)d_in[11];
    float* out = (float*)d_out;

    float *pE, *pP, *pT2, *pV, *pS1, *pR, *pAct, *pUp;
    cudaGetSymbolAddress((void**)&pE,  g_E);
    cudaGetSymbolAddress((void**)&pP,  g_P);
    cudaGetSymbolAddress((void**)&pT2, g_t2);
    cudaGetSymbolAddress((void**)&pV,  g_virtual);
    cudaGetSymbolAddress((void**)&pS1, g_S1);
    cudaGetSymbolAddress((void**)&pR,  g_R);
    cudaGetSymbolAddress((void**)&pAct, g_actln);
    cudaGetSymbolAddress((void**)&pUp,  g_upln);

    cudaFuncSetAttribute((const void*)mma_gemm<128,0,0,false,2>,
                         cudaFuncAttributeMaxDynamicSharedMemorySize, SMB128);
    cudaFuncSetAttribute((const void*)mma_gemm<128,2,1,false,2>,
                         cudaFuncAttributeMaxDynamicSharedMemorySize, SMB128);
    cudaFuncSetAttribute((const void*)mma_gemm<64,0,1,false,4>,
                         cudaFuncAttributeMaxDynamicSharedMemorySize, SMB64);
    cudaFuncSetAttribute((const void*)mma_gemm<128,1,1,true,2>,
                         cudaFuncAttributeMaxDynamicSharedMemorySize, SMB128);
    cudaFuncSetAttribute((const void*)mma_gemm<128,0,1,false,2>,
                         cudaFuncAttributeMaxDynamicSharedMemorySize, SMB128);
    cudaFuncSetAttribute((const void*)final_kernel,
                         cudaFuncAttributeMaxDynamicSharedMemorySize, SMB128);

    prep_kernel<<<BSN, 256>>>(resid, ln, pruned);
    bias_v_kernel<<<3, 256>>>(W_V, up_b_dec);
    bias_C_kernel<<<3, 256>>>(W_O);
    bias_g_kernel<<<FDN * 32 / 256, 256>>>(enc_W, enc_b, b_dec);

    // E_flat[768,2048] = W_O_flat[768,768] @ enc_W^T
    mma_gemm<128,0,0,false,2><<<dim3(16,6,1), 256, SMB128>>>(
        W_O, DN, 0, 0,
        enc_W, DN, 0, 0,
        pE, FDN, 0, 0,
        DN, 1, nullptr, 0);

    // P_flat[768,2048]: A = W_V pack, B = up_dec_W (k-major)
    mma_gemm<128,2,1,false,2><<<dim3(16,6,1), 256, SMB128>>>(
        W_V, 0, 0, 0,
        up_dec_W, FUN, 0, 0,
        pP, FUN, 0, 0,
        DN, 1, nullptr, 0);

    // t2[h] = act_ln @ W_V[h] : M=1024,N=64,K=768
    mma_gemm<64,0,1,false,4><<<dim3(1,8,HN), 256, SMB64>>>(
        pAct, DN, 0, 0,
        W_V, DHN, (long)DN*DHN, 0,
        pT2, DHN, (long)BSN*DHN, 0,
        DN, 1, nullptr, 0);

    // virtual[h] = mask .* (E[h]^T @ P[h]) : M=2048,N=2048,K=64
    mma_gemm<128,1,1,true,2><<<dim3(16,16,HN), 256, SMB128>>>(
        pE, FDN, (long)DHN*FDN, 0,
        pP, FUN, (long)DHN*FUN, 0,
        pV, FUN, (long)FDN*FUN, 0,
        DHN, 1, cmask, FUN);

    // S1[b,h] = probs[b,h] @ t2[h,b-rows] : M=256,N=64,K=256
    mma_gemm<64,0,1,false,4><<<dim3(1,2,4*HN), 256, SMB64>>>(
        probs, 256, (long)HN*256*256, (long)256*256,
        pT2, DHN, (long)256*DHN, (long)BSN*DHN,
        pS1, DHN, (long)HN*256*DHN, (long)256*DHN,
        256, HN, nullptr, 0);

    // R[b,h] = probs[b,h] @ up_ln[b] : M=256,N=2048,K=256
    mma_gemm<128,0,1,false,2><<<dim3(16,2,4*HN), 256, SMB128>>>(
        probs, 256, (long)HN*256*256, (long)256*256,
        pUp, FUN, (long)256*FUN, 0,
        pR, FUN, (long)HN*256*FUN, (long)256*FUN,
        256, HN, nullptr, 0);

    // out = sum_h (S1@E + R@virtual^T) + bias
    final_kernel<<<dim3(16,2,4), 256, SMB128>>>(out);
}

// round 12
// speedup vs baseline: 2.3944x; 1.0083x over previous
#include <cuda_runtime.h>
#include <cuda_fp16.h>
#include <cstdint>
#include <cstddef>

// ---------------------------------------------------------------------------
// SCAEAttention, rank-64 factorization, legacy mma.sync m16n8k16 fp16 with
// 3-pass hi/lo split. ALL operands pre-split into persistent fp16 hi/lo
// planes in gmem, so GEMM hot loops do no fp32<->fp16 conversion.
//
//  E[hk,f]    = W_O_flat @ enc_W^T                    (768,2048,768)
//  P[hk,u]    = W_Vpack @ up_dec_W                    (768,2048,768)
//  virtual[h] = mask .* (E[h]^T @ P[h])               (2048,2048,64)x12
//  t2[h]      = act_ln @ W_V[h]                       (1024,64,768)x12
//  S1[b,h]    = probs[b,h] @ t2[h,b-rows]             (256,64,256)x48
//  R[b,h]     = probs[b,h] @ up_ln[b]                 (256,2048,256)x48
//  Rcat = [R | S1] (K=2112), Vcat = [virtual | E^T]
//  out[b,q,f] = sum_h Rcat[b,h] @ Vcat[h]^T + bias0 + inv*g
// ---------------------------------------------------------------------------

#define HN 12
#define DHN 64
#define DN 768
#define FDN 2048
#define FUN 2048
#define BSN 1024
#define KC 2112            // FUN + DHN

#define LO_SCALE 2048.0f
#define LO_INV   (1.0f / 2048.0f)
#define STRD 40            // halves per smem row (32 + 8 pad)

// persistent fp16 hi/lo planes
__device__ __half g_Eh[DN * FDN],            g_El[DN * FDN];
__device__ __half g_Ph[DN * FUN],            g_Pl[DN * FUN];
__device__ __half g_t2h[HN * BSN * DHN],     g_t2l[HN * BSN * DHN];
__device__ __half g_Vh[(size_t)HN * FDN * KC], g_Vl[(size_t)HN * FDN * KC];
__device__ __half g_Rh[(size_t)4 * HN * 256 * KC], g_Rl[(size_t)4 * HN * 256 * KC];
__device__ __half g_acth[BSN * DN],          g_actl[BSN * DN];
__device__ __half g_uph[BSN * FUN],          g_upl[BSN * FUN];
__device__ __half g_prh[4 * HN * 256 * 256], g_prl[4 * HN * 256 * 256];
__device__ __half g_WOh[DN * DN],            g_WOl[DN * DN];
__device__ __half g_eWh[FDN * DN],           g_eWl[FDN * DN];
__device__ __half g_WVph[DN * DN],           g_WVpl[DN * DN];  // [hk][i]
__device__ __half g_WVbh[DN * DN],           g_WVbl[DN * DN];  // [h][i][kdh]
__device__ __half g_udh[DN * FUN],           g_udl[DN * FUN];
__device__ float g_inv[BSN];
__device__ float g_v[HN * DHN];
__device__ float g_C[DN];
__device__ float g_gvec[FDN];
__device__ float g_bias0[FDN];

// ------------------------------- helpers -----------------------------------
__device__ __forceinline__ void mma_f16(float (&c)[4], const uint32_t (&a)[4],
                                        const uint32_t (&b)[2])
{
    asm volatile(
        "mma.sync.aligned.m16n8k16.row.col.f32.f16.f16.f32 "
        "{%0,%1,%2,%3}, {%4,%5,%6,%7}, {%8,%9}, {%0,%1,%2,%3};"
        : "+f"(c[0]), "+f"(c[1]), "+f"(c[2]), "+f"(c[3])
        : "r"(a[0]), "r"(a[1]), "r"(a[2]), "r"(a[3]), "r"(b[0]), "r"(b[1]));
}

__device__ __forceinline__ void split_one(float v, __half& h, __half& l)
{
    h = __float2half_rn(v);
    l = __float2half_rn((v - __half2float(h)) * LO_SCALE);
}

__device__ __forceinline__ void split_pack(float x, float y,
                                           uint32_t& hi2, uint32_t& lo2)
{
    __half hx, lx, hy, ly;
    split_one(x, hx, lx);
    split_one(y, hy, ly);
    hi2 = ((uint32_t)__half_as_ushort(hy) << 16) | __half_as_ushort(hx);
    lo2 = ((uint32_t)__half_as_ushort(ly) << 16) | __half_as_ushort(lx);
}

// ------------------ staging: plane gmem -> regs -> smem --------------------
// MODE 0: X[m*ld + k] (k-fast); MODE 1: X[k*ld + m] (m-fast)
template <int ROWS, int MODE>
__device__ __forceinline__ void ld_tile_h(
    const __half* __restrict__ Xh, const __half* __restrict__ Xl,
    int ld, int k0, int row0, uint32_t* rh, uint32_t* rl)
{
    constexpr int IT = ROWS / 16;
#pragma unroll
    for (int t = 0; t < IT; t++) {
        int p = threadIdx.x + t * 256;
        size_t idx;
        if (MODE == 0) {
            int m = p >> 4, kp = (p & 15) * 2;
            idx = (size_t)(row0 + m) * ld + k0 + kp;
        } else {
            constexpr int MP = ROWS / 2;
            int k = p / MP, m2 = (p % MP) * 2;
            idx = (size_t)(k0 + k) * ld + row0 + m2;
        }
        rh[t] = *(const uint32_t*)(Xh + idx);
        rl[t] = *(const uint32_t*)(Xl + idx);
    }
}

template <int ROWS, int MODE>
__device__ __forceinline__ void st_tile_h(const uint32_t* rh, const uint32_t* rl,
                                          __half* hp, __half* lp)
{
    constexpr int IT = ROWS / 16;
#pragma unroll
    for (int t = 0; t < IT; t++) {
        int p = threadIdx.x + t * 256;
        if (MODE == 0) {
            int m = p >> 4, kp = (p & 15) * 2;
            *(uint32_t*)(hp + m * STRD + kp) = rh[t];
            *(uint32_t*)(lp + m * STRD + kp) = rl[t];
        } else {
            constexpr int MP = ROWS / 2;
            int k = p / MP, m2 = (p % MP) * 2;
            hp[m2 * STRD + k]       = __ushort_as_half((unsigned short)(rh[t] & 0xffff));
            hp[(m2 + 1) * STRD + k] = __ushort_as_half((unsigned short)(rh[t] >> 16));
            lp[m2 * STRD + k]       = __ushort_as_half((unsigned short)(rl[t] & 0xffff));
            lp[(m2 + 1) * STRD + k] = __ushort_as_half((unsigned short)(rl[t] >> 16));
        }
    }
}

// --------------------------- fp16x3 GEMM stage -----------------------------
template <int BN, int AMODE, int BMODE, int WM>
__device__ __forceinline__ void mma_stage(
    const __half* __restrict__ Agh, const __half* __restrict__ Agl, int lda,
    const __half* __restrict__ Bgh, const __half* __restrict__ Bgl, int ldb,
    int K, int tileM, int tileN,
    float (&hh)[8 / WM][BN * WM / 64][4],
    float (&ml)[8 / WM][BN * WM / 64][4],
    __half* sm)
{
    constexpr int WN = 8 / WM;
    constexpr int MT = 8 / WM;
    constexpr int NT = BN * WM / 64;
    constexpr int APL = 128 * STRD;
    constexpr int BPL = BN * STRD;
    constexpr int BUF = 2 * APL + 2 * BPL;

    const int lane = threadIdx.x & 31, warp = threadIdx.x >> 5;
    const int g = lane >> 2, tc = lane & 3;
    const int wm = (warp % WM) * (128 / WM);
    const int wn = (warp / WM) * (BN / WN);

    uint32_t raH[8], raL[8], rbH[BN / 16], rbL[BN / 16];

    auto stor = [&](int buf) {
        __half* base = sm + buf * BUF;
        st_tile_h<128, AMODE>(raH, raL, base, base + APL);
        st_tile_h<BN, BMODE>(rbH, rbL, base + 2 * APL, base + 2 * APL + BPL);
    };
    auto comp = [&](int buf) {
        __half* base = sm + buf * BUF;
        const __half* Ah = base;
        const __half* Al = base + APL;
        const __half* Bh = base + 2 * APL;
        const __half* Bl = base + 2 * APL + BPL;
#pragma unroll
        for (int ks = 0; ks < 32; ks += 16) {
            uint32_t afh[MT][4], afl[MT][4], bfh[NT][2], bfl[NT][2];
            const int c0 = ks + 2 * tc;
#pragma unroll
            for (int i = 0; i < MT; i++) {
                int r0 = wm + i * 16 + g;
                afh[i][0] = *(const uint32_t*)(Ah + r0 * STRD + c0);
                afh[i][1] = *(const uint32_t*)(Ah + (r0 + 8) * STRD + c0);
                afh[i][2] = *(const uint32_t*)(Ah + r0 * STRD + c0 + 8);
                afh[i][3] = *(const uint32_t*)(Ah + (r0 + 8) * STRD + c0 + 8);
                afl[i][0] = *(const uint32_t*)(Al + r0 * STRD + c0);
                afl[i][1] = *(const uint32_t*)(Al + (r0 + 8) * STRD + c0);
                afl[i][2] = *(const uint32_t*)(Al + r0 * STRD + c0 + 8);
                afl[i][3] = *(const uint32_t*)(Al + (r0 + 8) * STRD + c0 + 8);
            }
#pragma unroll
            for (int j = 0; j < NT; j++) {
                int n0 = wn + j * 8 + g;
                bfh[j][0] = *(const uint32_t*)(Bh + n0 * STRD + c0);
                bfh[j][1] = *(const uint32_t*)(Bh + n0 * STRD + c0 + 8);
                bfl[j][0] = *(const uint32_t*)(Bl + n0 * STRD + c0);
                bfl[j][1] = *(const uint32_t*)(Bl + n0 * STRD + c0 + 8);
            }
#pragma unroll
            for (int i = 0; i < MT; i++)
#pragma unroll
                for (int j = 0; j < NT; j++) {
                    mma_f16(hh[i][j], afh[i], bfh[j]);
                    mma_f16(ml[i][j], afh[i], bfl[j]);
                    mma_f16(ml[i][j], afl[i], bfh[j]);
                }
        }
    };

    const int niter = K / 32;
    ld_tile_h<128, AMODE>(Agh, Agl, lda, 0, tileM, raH, raL);
    ld_tile_h<BN, BMODE>(Bgh, Bgl, ldb, 0, tileN, rbH, rbL);
    stor(0);
    __syncthreads();
    for (int it = 0; it < niter; it++) {
        if (it + 1 < niter) {
            ld_tile_h<128, AMODE>(Agh, Agl, lda, (it + 1) * 32, tileM, raH, raL);
            ld_tile_h<BN, BMODE>(Bgh, Bgl, ldb, (it + 1) * 32, tileN, rbH, rbL);
        }
        comp(it & 1);
        if (it + 1 < niter) stor((it + 1) & 1);
        __syncthreads();
    }
}

// --------------------------- generic mma GEMM ------------------------------
// output: split fp16 plane pair, optional mask
template <int BN, int AMODE, int BMODE, bool MASK_, int WM>
__global__ void __launch_bounds__(256, 1) mma_gemm(
    const __half* __restrict__ Ah, const __half* __restrict__ Al,
    int lda, long sAo, long sAi,
    const __half* __restrict__ Bh, const __half* __restrict__ Bl,
    int ldb, long sBo, long sBi,
    __half* __restrict__ Ch, __half* __restrict__ Cl,
    int ldc, long sCo, long sCi,
    int K, int bsplit,
    const int* __restrict__ mask, int mld)
{
    constexpr int MT = 8 / WM;
    constexpr int NT = BN * WM / 64;
    extern __shared__ __half sm[];

    const int bz = blockIdx.z;
    const int bo = bz / bsplit, bi = bz - bo * bsplit;
    Ah += bo * sAo + bi * sAi;  Al += bo * sAo + bi * sAi;
    Bh += bo * sBo + bi * sBi;  Bl += bo * sBo + bi * sBi;
    Ch += bo * sCo + bi * sCi;  Cl += bo * sCo + bi * sCi;
    const int tileM = blockIdx.y * 128;
    const int tileN = blockIdx.x * BN;

    float hh[MT][NT][4] = {};
    float ml[MT][NT][4] = {};
    mma_stage<BN, AMODE, BMODE, WM>(Ah, Al, lda, Bh, Bl, ldb, K, tileM, tileN,
                                    hh, ml, sm);

    const int lane = threadIdx.x & 31, warp = threadIdx.x >> 5;
    const int g = lane >> 2, tc = lane & 3;
    const int wm = (warp % WM) * (128 / WM);
    const int wn = (warp / WM) * (BN / (8 / WM));

#pragma unroll
    for (int i = 0; i < MT; i++) {
        int m0 = tileM + wm + i * 16 + g;
#pragma unroll
        for (int j = 0; j < NT; j++) {
            int n0 = tileN + wn + j * 8 + 2 * tc;
            float v0 = hh[i][j][0] + ml[i][j][0] * LO_INV;
            float v1 = hh[i][j][1] + ml[i][j][1] * LO_INV;
            float v2 = hh[i][j][2] + ml[i][j][2] * LO_INV;
            float v3 = hh[i][j][3] + ml[i][j][3] * LO_INV;
            if (MASK_) {
                v0 *= (float)mask[(size_t)m0 * mld + n0];
                v1 *= (float)mask[(size_t)m0 * mld + n0 + 1];
                v2 *= (float)mask[(size_t)(m0 + 8) * mld + n0];
                v3 *= (float)mask[(size_t)(m0 + 8) * mld + n0 + 1];
            }
            uint32_t h2, l2;
            split_pack(v0, v1, h2, l2);
            *(uint32_t*)(Ch + (size_t)m0 * ldc + n0) = h2;
            *(uint32_t*)(Cl + (size_t)m0 * ldc + n0) = l2;
            split_pack(v2, v3, h2, l2);
            *(uint32_t*)(Ch + (size_t)(m0 + 8) * ldc + n0) = h2;
            *(uint32_t*)(Cl + (size_t)(m0 + 8) * ldc + n0) = l2;
        }
    }
}

// --------------------------- final fused kernel ----------------------------
// out[b,q,f] = sum_h Rcat[b,h] @ Vcat[h]^T  (K=2112) + bias0 + inv*g
__global__ void __launch_bounds__(256, 1) final_kernel(float* __restrict__ out)
{
    constexpr int WM = 2, MT = 4, NT = 4;
    extern __shared__ __half sm[];

    const int b = blockIdx.z;
    const int tileM = blockIdx.y * 128;
    const int tileN = blockIdx.x * 128;

    float hh[MT][NT][4] = {};
    float ml[MT][NT][4] = {};

    for (int h = 0; h < HN; ++h) {
        size_t ao = (size_t)(b * HN + h) * 256 * KC;
        size_t bo = (size_t)h * FDN * KC;
        mma_stage<128, 0, 0, WM>(g_Rh + ao, g_Rl + ao, KC,
                                 g_Vh + bo, g_Vl + bo, KC,
                                 KC, tileM, tileN, hh, ml, sm);
    }

    const int lane = threadIdx.x & 31, warp = threadIdx.x >> 5;
    const int g = lane >> 2, tc = lane & 3;
    const int wm = (warp % WM) * 64;
    const int wn = (warp / WM) * 32;

#pragma unroll
    for (int i = 0; i < MT; i++) {
        int q0 = tileM + wm + i * 16 + g;
        float inv0 = g_inv[b * 256 + q0];
        float inv1 = g_inv[b * 256 + q0 + 8];
#pragma unroll
        for (int j = 0; j < NT; j++) {
            int f0 = tileN + wn + j * 8 + 2 * tc;
            float bA = g_bias0[f0], bB = g_bias0[f0 + 1];
            float gA = g_gvec[f0],  gB = g_gvec[f0 + 1];
            out[((size_t)b * 256 + q0) * FDN + f0] =
                hh[i][j][0] + ml[i][j][0] * LO_INV + bA + inv0 * gA;
            out[((size_t)b * 256 + q0) * FDN + f0 + 1] =
                hh[i][j][1] + ml[i][j][1] * LO_INV + bB + inv0 * gB;
            out[((size_t)b * 256 + q0 + 8) * FDN + f0] =
                hh[i][j][2] + ml[i][j][2] * LO_INV + bA + inv1 * gA;
            out[((size_t)b * 256 + q0 + 8) * FDN + f0 + 1] =
                hh[i][j][3] + ml[i][j][3] * LO_INV + bB + inv1 * gB;
        }
    }
}

// --------------------------- small kernels ---------------------------------
__global__ void prep_kernel(const float* __restrict__ resid,
                            const float* __restrict__ ln,
                            const float* __restrict__ pruned)
{
    int row = blockIdx.x;
    float inv = 1.0f / ln[row];
    if (threadIdx.x == 0) g_inv[row] = inv;
    for (int d = threadIdx.x; d < DN; d += blockDim.x) {
        float v = resid[(size_t)row * DN + d] * inv;
        split_one(v, g_acth[(size_t)row * DN + d], g_actl[(size_t)row * DN + d]);
    }
    for (int u = threadIdx.x; u < FUN; u += blockDim.x) {
        float v = pruned[(size_t)row * FUN + u] * inv;
        split_one(v, g_uph[(size_t)row * FUN + u], g_upl[(size_t)row * FUN + u]);
    }
}

__global__ void split_arr(const float* __restrict__ src,
                          __half* __restrict__ dh, __half* __restrict__ dl, int n)
{
    int i = blockIdx.x * blockDim.x + threadIdx.x;
    if (i < n) split_one(src[i], dh[i], dl[i]);
}

// W_V [h][i][k] -> packed [hk][i]
__global__ void split_wvp(const float* __restrict__ W_V)
{
    int d = blockIdx.x * blockDim.x + threadIdx.x;
    if (d >= DN * DN) return;
    int hk = d / DN, ii = d - hk * DN;
    float v = W_V[(size_t)(hk >> 6) * (DN * DHN) + (size_t)ii * DHN + (hk & 63)];
    split_one(v, g_WVph[d], g_WVpl[d]);
}

// Vcat[h][f][2048+c] = E[h*64+c][f]  (smem transpose, 64x64 tiles)
__global__ void et_kernel()
{
    __shared__ __half sh[64 * 66], sl[64 * 66];
    const int h = blockIdx.x;
    const int f0 = blockIdx.y * 64;
#pragma unroll
    for (int t = 0; t < 16; t++) {
        int idx = threadIdx.x + t * 256;
        int c = idx >> 6, f = idx & 63;
        sh[c * 66 + f] = g_Eh[(size_t)(h * 64 + c) * FDN + f0 + f];
        sl[c * 66 + f] = g_El[(size_t)(h * 64 + c) * FDN + f0 + f];
    }
    __syncthreads();
#pragma unroll
    for (int t = 0; t < 16; t++) {
        int idx = threadIdx.x + t * 256;
        int f = idx >> 6, c = idx & 63;
        size_t o = ((size_t)h * FDN + f0 + f) * KC + FUN + c;
        g_Vh[o] = sh[c * 66 + f];
        g_Vl[o] = sl[c * 66 + f];
    }
}

__global__ void bias_v_kernel(const float* __restrict__ W_V,
                              const float* __restrict__ up_b_dec)
{
    int hk = blockIdx.x * blockDim.x + threadIdx.x;
    if (hk >= HN * DHN) return;
    int h = hk >> 6, k = hk & 63;
    const float* base = W_V + (size_t)h * DN * DHN + k;
    float s = 0.f;
    for (int m = 0; m < DN; m++) s = fmaf(base[(size_t)m * DHN], up_b_dec[m], s);
    g_v[hk] = s;
}

__global__ void bias_C_kernel(const float* __restrict__ W_O)
{
    int d = blockIdx.x * blockDim.x + threadIdx.x;
    if (d >= DN) return;
    float s = 0.f;
    for (int hk = 0; hk < HN * DHN; hk++)
        s = fmaf(g_v[hk], W_O[(size_t)hk * DN + d], s);
    g_C[d] = s;
}

__global__ void bias_g_kernel(const float* __restrict__ enc_W,
                              const float* __restrict__ enc_b,
                              const float* __restrict__ b_dec)
{
    int w = (blockIdx.x * blockDim.x + threadIdx.x) >> 5;
    int lane = threadIdx.x & 31;
    if (w >= FDN) return;
    const float* row = enc_W + (size_t)w * DN;
    float sg = 0.f, sb = 0.f;
    for (int d = lane; d < DN; d += 32) {
        float r = row[d];
        sg = fmaf(r, g_C[d], sg);
        sb = fmaf(r, b_dec[d], sb);
    }
#pragma unroll
    for (int o = 16; o; o >>= 1) {
        sg += __shfl_xor_sync(0xffffffffu, sg, o);
        sb += __shfl_xor_sync(0xffffffffu, sb, o);
    }
    if (lane == 0) { g_gvec[w] = sg; g_bias0[w] = enc_b[w] - sb; }
}

// --------------------------- launch ----------------------------------------
static constexpr int SMB128 = 2 * (2 * 128 * STRD + 2 * 128 * STRD) * 2; // 81920
static constexpr int SMB64  = 2 * (2 * 128 * STRD + 2 * 64 * STRD) * 2;  // 61440

template <typename T>
static const __half* dsym(T& sym) {
    void* p = nullptr;
    cudaGetSymbolAddress(&p, sym);
    return (const __half*)p;
}

extern "C" void kernel_launch(void* const* d_in, const int* in_sizes, int n_in,
                              void* d_out, int out_size)
{
    (void)in_sizes; (void)n_in; (void)out_size;
    const float* resid    = (const float*)d_in[0];
    const float* ln       = (const float*)d_in[1];
    const float* probs    = (const float*)d_in[2];
    const float* W_O      = (const float*)d_in[3];
    const float* W_V      = (const float*)d_in[4];
    const float* enc_W    = (const float*)d_in[5];
    const float* enc_b    = (const float*)d_in[6];
    const float* b_dec    = (const float*)d_in[7];
    const float* up_dec_W = (const float*)d_in[8];
    const float* up_b_dec = (const float*)d_in[9];
    const float* pruned   = (const float*)d_in[10];
    const int*   cmask    = (const int*)d_in[11];
    float* out = (float*)d_out;

    const __half *pEh = dsym(g_Eh), *pEl = dsym(g_El);
    const __half *pPh = dsym(g_Ph), *pPl = dsym(g_Pl);
    const __half *pT2h = dsym(g_t2h), *pT2l = dsym(g_t2l);
    const __half *pVh = dsym(g_Vh), *pVl = dsym(g_Vl);
    const __half *pRh = dsym(g_Rh), *pRl = dsym(g_Rl);
    const __half *pAch = dsym(g_acth), *pAcl = dsym(g_actl);
    const __half *pUph = dsym(g_uph), *pUpl = dsym(g_upl);
    const __half *pPrh = dsym(g_prh), *pPrl = dsym(g_prl);
    const __half *pWOh = dsym(g_WOh), *pWOl = dsym(g_WOl);
    const __half *pEWh = dsym(g_eWh), *pEWl = dsym(g_eWl);
    const __half *pWVph = dsym(g_WVph), *pWVpl = dsym(g_WVpl);
    const __half *pWVbh = dsym(g_WVbh), *pWVbl = dsym(g_WVbl);
    const __half *pUdh = dsym(g_udh), *pUdl = dsym(g_udl);

    cudaFuncSetAttribute((const void*)mma_gemm<128,0,0,false,2>,
                         cudaFuncAttributeMaxDynamicSharedMemorySize, SMB128);
    cudaFuncSetAttribute((const void*)mma_gemm<128,0,1,false,2>,
                         cudaFuncAttributeMaxDynamicSharedMemorySize, SMB128);
    cudaFuncSetAttribute((const void*)mma_gemm<64,0,1,false,4>,
                         cudaFuncAttributeMaxDynamicSharedMemorySize, SMB64);
    cudaFuncSetAttribute((const void*)mma_gemm<128,1,1,true,2>,
                         cudaFuncAttributeMaxDynamicSharedMemorySize, SMB128);
    cudaFuncSetAttribute((const void*)final_kernel,
                         cudaFuncAttributeMaxDynamicSharedMemorySize, SMB128);

    // input splits + elementwise prep
    prep_kernel<<<BSN, 256>>>(resid, ln, pruned);
    split_arr<<<(DN*DN + 255)/256, 256>>>(W_O, (__half*)pWOh, (__half*)pWOl, DN*DN);
    split_arr<<<(FDN*DN + 255)/256, 256>>>(enc_W, (__half*)pEWh, (__half*)pEWl, FDN*DN);
    split_arr<<<(DN*DN + 255)/256, 256>>>(W_V, (__half*)pWVbh, (__half*)pWVbl, DN*DN);
    split_arr<<<(DN*FUN + 255)/256, 256>>>(up_dec_W, (__half*)pUdh, (__half*)pUdl, DN*FUN);
    split_arr<<<(4*HN*256*256 + 255)/256, 256>>>(probs, (__half*)pPrh, (__half*)pPrl, 4*HN*256*256);
    split_wvp<<<(DN*DN + 255)/256, 256>>>(W_V);

    // rank-1 bias chain (fp32)
    bias_v_kernel<<<3, 256>>>(W_V, up_b_dec);
    bias_C_kernel<<<3, 256>>>(W_O);
    bias_g_kernel<<<FDN * 32 / 256, 256>>>(enc_W, enc_b, b_dec);

    // E_flat[768,2048] = W_O_flat @ enc_W^T
    mma_gemm<128,0,0,false,2><<<dim3(16,6,1), 256, SMB128>>>(
        pWOh, pWOl, DN, 0, 0,
        pEWh, pEWl, DN, 0, 0,
        (__half*)pEh, (__half*)pEl, FDN, 0, 0,
        DN, 1, nullptr, 0);

    // P_flat[768,2048] = W_Vpack @ up_dec_W
    mma_gemm<128,0,1,false,2><<<dim3(16,6,1), 256, SMB128>>>(
        pWVph, pWVpl, DN, 0, 0,
        pUdh, pUdl, FUN, 0, 0,
        (__half*)pPh, (__half*)pPl, FUN, 0, 0,
        DN, 1, nullptr, 0);

    // Vcat[...][2048..2111] = E^T
    et_kernel<<<dim3(HN, FDN/64), 256>>>();

    // t2[h] = act_ln @ W_V[h] : M=1024,N=64,K=768
    mma_gemm<64,0,1,false,4><<<dim3(1,8,HN), 256, SMB64>>>(
        pAch, pAcl, DN, 0, 0,
        pWVbh, pWVbl, DHN, (long)DN*DHN, 0,
        (__half*)pT2h, (__half*)pT2l, DHN, (long)BSN*DHN, 0,
        DN, 1, nullptr, 0);

    // Vcat[...][0..2047] = mask .* (E[h]^T @ P[h]) : M=2048,N=2048,K=64
    mma_gemm<128,1,1,true,2><<<dim3(16,16,HN), 256, SMB128>>>(
        pEh, pEl, FDN, (long)DHN*FDN, 0,
        pPh, pPl, FUN, (long)DHN*FUN, 0,
        (__half*)pVh, (__half*)pVl, KC, (long)FDN*KC, 0,
        DHN, 1, cmask, FUN);

    // Rcat[...][2048..2111] = S1 = probs @ t2 : M=256,N=64,K=256
    mma_gemm<64,0,1,false,4><<<dim3(1,2,4*HN), 256, SMB64>>>(
        pPrh, pPrl, 256, (long)HN*256*256, (long)256*256,
        pT2h, pT2l, DHN, (long)256*DHN, (long)BSN*DHN,
        (__half*)pRh + FUN, (__half*)pRl + FUN, KC, (long)HN*256*KC, (long)256*KC,
        256, HN, nullptr, 0);

    // Rcat[...][0..2047] = R = probs @ up_ln : M=256,N=2048,K=256
    mma_gemm<128,0,1,false,2><<<dim3(16,2,4*HN), 256, SMB128>>>(
        pPrh, pPrl, 256, (long)HN*256*256, (long)256*256,
        pUph, pUpl, FUN, (long)256*FUN, 0,
        (__half*)pRh, (__half*)pRl, KC, (long)HN*256*KC, (long)256*KC,
        256, HN, nullptr, 0);

    // out = sum_h Rcat @ Vcat^T + bias
    final_kernel<<<dim3(16,2,4), 256, SMB128>>>(out);
}

// round 16
// speedup vs baseline: 3.1068x; 1.2975x over previous
#include <cuda_runtime.h>
#include <cuda_fp16.h>
#include <cstdint>
#include <cstddef>

// ---------------------------------------------------------------------------
// SCAEAttention, rank-64 factorization, legacy mma.sync m16n8k16 fp16.
// Upstream GEMMs: 3-pass hi/lo split. Final (dominant) GEMM: 2-pass
// (hi*hi + hi*lo_B), A side enters as fp16 hi plane only.
// Fragment loads via ldmatrix.m8n8 (LDSM) to cut shared-load issue count.
//
//  E[hk,f]    = W_O_flat @ enc_W^T                    (768,2048,768)
//  P[hk,u]    = W_Vpack @ up_dec_W                    (768,2048,768)
//  virtual[h] = mask .* (E[h]^T @ P[h])               (2048,2048,64)x12
//  t2[h]      = act_ln @ W_V[h]                       (1024,64,768)x12
//  S1[b,h]    = probs[b,h] @ t2[h,b-rows]             (256,64,256)x48
//  R[b,h]     = probs[b,h] @ up_ln[b]                 (256,2048,256)x48
//  Rcat = [R | S1] (K=2112), Vcat = [virtual | E^T]
//  out[b,q,f] = sum_h Rcat[b,h] @ Vcat[h]^T + bias0 + inv*g
// ---------------------------------------------------------------------------

#define HN 12
#define DHN 64
#define DN 768
#define FDN 2048
#define FUN 2048
#define BSN 1024
#define KC 2112            // FUN + DHN

#define LO_SCALE 2048.0f
#define LO_INV   (1.0f / 2048.0f)
#define STRD 40            // halves per smem row (32 + 8 pad); 80B stride

// persistent fp16 hi/lo planes
__device__ __half g_Eh[DN * FDN],            g_El[DN * FDN];
__device__ __half g_Ph[DN * FUN],            g_Pl[DN * FUN];
__device__ __half g_t2h[HN * BSN * DHN],     g_t2l[HN * BSN * DHN];
__device__ __half g_Vh[(size_t)HN * FDN * KC], g_Vl[(size_t)HN * FDN * KC];
__device__ __half g_Rh[(size_t)4 * HN * 256 * KC], g_Rl[(size_t)4 * HN * 256 * KC];
__device__ __half g_acth[BSN * DN],          g_actl[BSN * DN];
__device__ __half g_uph[BSN * FUN],          g_upl[BSN * FUN];
__device__ __half g_prh[4 * HN * 256 * 256], g_prl[4 * HN * 256 * 256];
__device__ __half g_WOh[DN * DN],            g_WOl[DN * DN];
__device__ __half g_eWh[FDN * DN],           g_eWl[FDN * DN];
__device__ __half g_WVph[DN * DN],           g_WVpl[DN * DN];  // [hk][i]
__device__ __half g_WVbh[DN * DN],           g_WVbl[DN * DN];  // [h][i][kdh]
__device__ __half g_udh[DN * FUN],           g_udl[DN * FUN];
__device__ float g_inv[BSN];
__device__ float g_v[HN * DHN];
__device__ float g_C[DN];
__device__ float g_gvec[FDN];
__device__ float g_bias0[FDN];

// ------------------------------- helpers -----------------------------------
__device__ __forceinline__ void mma_f16(float (&c)[4], const uint32_t (&a)[4],
                                        const uint32_t (&b)[2])
{
    asm volatile(
        "mma.sync.aligned.m16n8k16.row.col.f32.f16.f16.f32 "
        "{%0,%1,%2,%3}, {%4,%5,%6,%7}, {%8,%9}, {%0,%1,%2,%3};"
        : "+f"(c[0]), "+f"(c[1]), "+f"(c[2]), "+f"(c[3])
        : "r"(a[0]), "r"(a[1]), "r"(a[2]), "r"(a[3]), "r"(b[0]), "r"(b[1]));
}

__device__ __forceinline__ void ldsm_x4(uint32_t (&r)[4], uint32_t addr)
{
    asm volatile("ldmatrix.sync.aligned.m8n8.x4.shared.b16 {%0,%1,%2,%3}, [%4];"
                 : "=r"(r[0]), "=r"(r[1]), "=r"(r[2]), "=r"(r[3]) : "r"(addr));
}

__device__ __forceinline__ uint32_t smem_u32(const void* p)
{
    uint32_t a;
    asm("{ .reg .u64 t; cvta.to.shared.u64 t, %1; cvt.u32.u64 %0, t; }"
        : "=r"(a) : "l"(p));
    return a;
}

__device__ __forceinline__ void split_one(float v, __half& h, __half& l)
{
    h = __float2half_rn(v);
    l = __float2half_rn((v - __half2float(h)) * LO_SCALE);
}

__device__ __forceinline__ void split_pack(float x, float y,
                                           uint32_t& hi2, uint32_t& lo2)
{
    __half hx, lx, hy, ly;
    split_one(x, hx, lx);
    split_one(y, hy, ly);
    hi2 = ((uint32_t)__half_as_ushort(hy) << 16) | __half_as_ushort(hx);
    lo2 = ((uint32_t)__half_as_ushort(ly) << 16) | __half_as_ushort(lx);
}

// ------------------ staging: plane gmem -> regs -> smem --------------------
// MODE 0: X[m*ld + k] (k-fast); MODE 1: X[k*ld + m] (m-fast)
template <int ROWS, int MODE, bool LO>
__device__ __forceinline__ void ld_tile_h(
    const __half* __restrict__ Xh, const __half* __restrict__ Xl,
    int ld, int k0, int row0, uint32_t* rh, uint32_t* rl)
{
    constexpr int IT = ROWS / 16;
#pragma unroll
    for (int t = 0; t < IT; t++) {
        int p = threadIdx.x + t * 256;
        size_t idx;
        if (MODE == 0) {
            int m = p >> 4, kp = (p & 15) * 2;
            idx = (size_t)(row0 + m) * ld + k0 + kp;
        } else {
            constexpr int MP = ROWS / 2;
            int k = p / MP, m2 = (p % MP) * 2;
            idx = (size_t)(k0 + k) * ld + row0 + m2;
        }
        rh[t] = *(const uint32_t*)(Xh + idx);
        if (LO) rl[t] = *(const uint32_t*)(Xl + idx);
    }
}

template <int ROWS, int MODE, bool LO>
__device__ __forceinline__ void st_tile_h(const uint32_t* rh, const uint32_t* rl,
                                          __half* hp, __half* lp)
{
    constexpr int IT = ROWS / 16;
#pragma unroll
    for (int t = 0; t < IT; t++) {
        int p = threadIdx.x + t * 256;
        if (MODE == 0) {
            int m = p >> 4, kp = (p & 15) * 2;
            *(uint32_t*)(hp + m * STRD + kp) = rh[t];
            if (LO) *(uint32_t*)(lp + m * STRD + kp) = rl[t];
        } else {
            constexpr int MP = ROWS / 2;
            int k = p / MP, m2 = (p % MP) * 2;
            hp[m2 * STRD + k]       = __ushort_as_half((unsigned short)(rh[t] & 0xffff));
            hp[(m2 + 1) * STRD + k] = __ushort_as_half((unsigned short)(rh[t] >> 16));
            if (LO) {
                lp[m2 * STRD + k]       = __ushort_as_half((unsigned short)(rl[t] & 0xffff));
                lp[(m2 + 1) * STRD + k] = __ushort_as_half((unsigned short)(rl[t] >> 16));
            }
        }
    }
}

// --------------------------- fp16 split GEMM stage -------------------------
// PASSES==3: hh += Ah*Bh, ml += Ah*Bl + Al*Bh  (A hi+lo staged)
// PASSES==2: hh += Ah*Bh, ml += Ah*Bl          (A hi only staged)
template <int BN, int AMODE, int BMODE, int WM, int PASSES>
__device__ __forceinline__ void mma_stage(
    const __half* __restrict__ Agh, const __half* __restrict__ Agl, int lda,
    const __half* __restrict__ Bgh, const __half* __restrict__ Bgl, int ldb,
    int K, int tileM, int tileN,
    float (&hh)[8 / WM][BN * WM / 64][4],
    float (&ml)[8 / WM][BN * WM / 64][4],
    __half* sm)
{
    constexpr int WN = 8 / WM;
    constexpr int MT = 8 / WM;
    constexpr int NT = BN * WM / 64;
    constexpr bool ALO = (PASSES == 3);
    constexpr int APLANES = ALO ? 2 : 1;
    constexpr int APL = 128 * STRD;
    constexpr int BPL = BN * STRD;
    constexpr int BUF = APLANES * APL + 2 * BPL;   // halves per buffer

    const int lane = threadIdx.x & 31, warp = threadIdx.x >> 5;
    const int wm = (warp % WM) * (128 / WM);
    const int wn = (warp / WM) * (BN / WN);

    const uint32_t smu = smem_u32(sm);

    // ldmatrix lane-dependent byte offsets (within a plane)
    uint32_t aOff[MT], bOff[NT / 2];
#pragma unroll
    for (int i = 0; i < MT; i++)
        aOff[i] = (uint32_t)(((wm + i * 16 + (lane & 15)) * STRD
                              + ((lane >> 4) & 1) * 8) * 2);
#pragma unroll
    for (int jp = 0; jp < NT / 2; jp++)
        bOff[jp] = (uint32_t)(((wn + (jp * 2 + ((lane >> 4) & 1)) * 8 + (lane & 7)) * STRD
                               + ((lane >> 3) & 1) * 8) * 2);

    uint32_t raH[8], raL[ALO ? 8 : 1], rbH[BN / 16], rbL[BN / 16];

    auto stor = [&](int buf) {
        __half* base = sm + buf * BUF;
        st_tile_h<128, AMODE, ALO>(raH, raL, base, base + APL);
        st_tile_h<BN, BMODE, true>(rbH, rbL, base + APLANES * APL,
                                   base + APLANES * APL + BPL);
    };
    auto comp = [&](int buf) {
        const uint32_t aBaseH = smu + (uint32_t)(buf * BUF) * 2;
        const uint32_t aBaseL = aBaseH + APL * 2;
        const uint32_t bBaseH = aBaseH + APLANES * APL * 2;
        const uint32_t bBaseL = bBaseH + BPL * 2;
#pragma unroll
        for (int ks = 0; ks < 32; ks += 16) {
            uint32_t afh[MT][4], afl[ALO ? MT : 1][4], bfh[NT][2], bfl[NT][2];
#pragma unroll
            for (int i = 0; i < MT; i++)
                ldsm_x4(afh[i], aBaseH + aOff[i] + ks * 2);
            if (ALO) {
#pragma unroll
                for (int i = 0; i < MT; i++)
                    ldsm_x4(afl[i], aBaseL + aOff[i] + ks * 2);
            }
#pragma unroll
            for (int jp = 0; jp < NT / 2; jp++) {
                uint32_t t[4];
                ldsm_x4(t, bBaseH + bOff[jp] + ks * 2);
                bfh[jp * 2][0] = t[0]; bfh[jp * 2][1] = t[1];
                bfh[jp * 2 + 1][0] = t[2]; bfh[jp * 2 + 1][1] = t[3];
                ldsm_x4(t, bBaseL + bOff[jp] + ks * 2);
                bfl[jp * 2][0] = t[0]; bfl[jp * 2][1] = t[1];
                bfl[jp * 2 + 1][0] = t[2]; bfl[jp * 2 + 1][1] = t[3];
            }
#pragma unroll
            for (int i = 0; i < MT; i++)
#pragma unroll
                for (int j = 0; j < NT; j++) {
                    mma_f16(hh[i][j], afh[i], bfh[j]);
                    mma_f16(ml[i][j], afh[i], bfl[j]);
                    if (ALO) mma_f16(ml[i][j], afl[i], bfh[j]);
                }
        }
    };

    const int niter = K / 32;
    ld_tile_h<128, AMODE, ALO>(Agh, Agl, lda, 0, tileM, raH, raL);
    ld_tile_h<BN, BMODE, true>(Bgh, Bgl, ldb, 0, tileN, rbH, rbL);
    stor(0);
    __syncthreads();
    for (int it = 0; it < niter; it++) {
        if (it + 1 < niter) {
            ld_tile_h<128, AMODE, ALO>(Agh, Agl, lda, (it + 1) * 32, tileM, raH, raL);
            ld_tile_h<BN, BMODE, true>(Bgh, Bgl, ldb, (it + 1) * 32, tileN, rbH, rbL);
        }
        comp(it & 1);
        if (it + 1 < niter) stor((it + 1) & 1);
        __syncthreads();
    }
}

// --------------------------- generic mma GEMM (3-pass) ---------------------
template <int BN, int AMODE, int BMODE, bool MASK_, int WM>
__global__ void __launch_bounds__(256, 1) mma_gemm(
    const __half* __restrict__ Ah, const __half* __restrict__ Al,
    int lda, long sAo, long sAi,
    const __half* __restrict__ Bh, const __half* __restrict__ Bl,
    int ldb, long sBo, long sBi,
    __half* __restrict__ Ch, __half* __restrict__ Cl,
    int ldc, long sCo, long sCi,
    int K, int bsplit,
    const int* __restrict__ mask, int mld)
{
    constexpr int MT = 8 / WM;
    constexpr int NT = BN * WM / 64;
    extern __shared__ __half sm[];

    const int bz = blockIdx.z;
    const int bo = bz / bsplit, bi = bz - bo * bsplit;
    Ah += bo * sAo + bi * sAi;  Al += bo * sAo + bi * sAi;
    Bh += bo * sBo + bi * sBi;  Bl += bo * sBo + bi * sBi;
    Ch += bo * sCo + bi * sCi;  Cl += bo * sCo + bi * sCi;
    const int tileM = blockIdx.y * 128;
    const int tileN = blockIdx.x * BN;

    float hh[MT][NT][4] = {};
    float ml[MT][NT][4] = {};
    mma_stage<BN, AMODE, BMODE, WM, 3>(Ah, Al, lda, Bh, Bl, ldb, K, tileM, tileN,
                                       hh, ml, sm);

    const int lane = threadIdx.x & 31, warp = threadIdx.x >> 5;
    const int g = lane >> 2, tc = lane & 3;
    const int wm = (warp % WM) * (128 / WM);
    const int wn = (warp / WM) * (BN / (8 / WM));

#pragma unroll
    for (int i = 0; i < MT; i++) {
        int m0 = tileM + wm + i * 16 + g;
#pragma unroll
        for (int j = 0; j < NT; j++) {
            int n0 = tileN + wn + j * 8 + 2 * tc;
            float v0 = hh[i][j][0] + ml[i][j][0] * LO_INV;
            float v1 = hh[i][j][1] + ml[i][j][1] * LO_INV;
            float v2 = hh[i][j][2] + ml[i][j][2] * LO_INV;
            float v3 = hh[i][j][3] + ml[i][j][3] * LO_INV;
            if (MASK_) {
                v0 *= (float)mask[(size_t)m0 * mld + n0];
                v1 *= (float)mask[(size_t)m0 * mld + n0 + 1];
                v2 *= (float)mask[(size_t)(m0 + 8) * mld + n0];
                v3 *= (float)mask[(size_t)(m0 + 8) * mld + n0 + 1];
            }
            uint32_t h2, l2;
            split_pack(v0, v1, h2, l2);
            *(uint32_t*)(Ch + (size_t)m0 * ldc + n0) = h2;
            *(uint32_t*)(Cl + (size_t)m0 * ldc + n0) = l2;
            split_pack(v2, v3, h2, l2);
            *(uint32_t*)(Ch + (size_t)(m0 + 8) * ldc + n0) = h2;
            *(uint32_t*)(Cl + (size_t)(m0 + 8) * ldc + n0) = l2;
        }
    }
}

// --------------------------- final fused kernel (2-pass) -------------------
// out[b,q,f] = sum_h Rcat_hi[b,h] @ (Vcat_hi + Vcat_lo/2048)[h]^T + bias
__global__ void __launch_bounds__(256, 1) final_kernel(float* __restrict__ out)
{
    constexpr int WM = 2, MT = 4, NT = 4;
    extern __shared__ __half sm[];

    const int b = blockIdx.z;
    const int tileM = blockIdx.y * 128;
    const int tileN = blockIdx.x * 128;

    float hh[MT][NT][4] = {};
    float ml[MT][NT][4] = {};

    for (int h = 0; h < HN; ++h) {
        size_t ao = (size_t)(b * HN + h) * 256 * KC;
        size_t bo = (size_t)h * FDN * KC;
        mma_stage<128, 0, 0, WM, 2>(g_Rh + ao, g_Rh + ao, KC,
                                    g_Vh + bo, g_Vl + bo, KC,
                                    KC, tileM, tileN, hh, ml, sm);
    }

    const int lane = threadIdx.x & 31, warp = threadIdx.x >> 5;
    const int g = lane >> 2, tc = lane & 3;
    const int wm = (warp % WM) * 64;
    const int wn = (warp / WM) * 32;

#pragma unroll
    for (int i = 0; i < MT; i++) {
        int q0 = tileM + wm + i * 16 + g;
        float inv0 = g_inv[b * 256 + q0];
        float inv1 = g_inv[b * 256 + q0 + 8];
#pragma unroll
        for (int j = 0; j < NT; j++) {
            int f0 = tileN + wn + j * 8 + 2 * tc;
            float bA = g_bias0[f0], bB = g_bias0[f0 + 1];
            float gA = g_gvec[f0],  gB = g_gvec[f0 + 1];
            out[((size_t)b * 256 + q0) * FDN + f0] =
                hh[i][j][0] + ml[i][j][0] * LO_INV + bA + inv0 * gA;
            out[((size_t)b * 256 + q0) * FDN + f0 + 1] =
                hh[i][j][1] + ml[i][j][1] * LO_INV + bB + inv0 * gB;
            out[((size_t)b * 256 + q0 + 8) * FDN + f0] =
                hh[i][j][2] + ml[i][j][2] * LO_INV + bA + inv1 * gA;
            out[((size_t)b * 256 + q0 + 8) * FDN + f0 + 1] =
                hh[i][j][3] + ml[i][j][3] * LO_INV + bB + inv1 * gB;
        }
    }
}

// --------------------------- small kernels ---------------------------------
__global__ void prep_kernel(const float* __restrict__ resid,
                            const float* __restrict__ ln,
                            const float* __restrict__ pruned)
{
    int row = blockIdx.x;
    float inv = 1.0f / ln[row];
    if (threadIdx.x == 0) g_inv[row] = inv;
    for (int d = threadIdx.x; d < DN; d += blockDim.x) {
        float v = resid[(size_t)row * DN + d] * inv;
        split_one(v, g_acth[(size_t)row * DN + d], g_actl[(size_t)row * DN + d]);
    }
    for (int u = threadIdx.x; u < FUN; u += blockDim.x) {
        float v = pruned[(size_t)row * FUN + u] * inv;
        split_one(v, g_uph[(size_t)row * FUN + u], g_upl[(size_t)row * FUN + u]);
    }
}

__global__ void split_arr(const float* __restrict__ src,
                          __half* __restrict__ dh, __half* __restrict__ dl, int n)
{
    int i = blockIdx.x * blockDim.x + threadIdx.x;
    if (i < n) split_one(src[i], dh[i], dl[i]);
}

// W_V [h][i][k] -> packed [hk][i]
__global__ void split_wvp(const float* __restrict__ W_V)
{
    int d = blockIdx.x * blockDim.x + threadIdx.x;
    if (d >= DN * DN) return;
    int hk = d / DN, ii = d - hk * DN;
    float v = W_V[(size_t)(hk >> 6) * (DN * DHN) + (size_t)ii * DHN + (hk & 63)];
    split_one(v, g_WVph[d], g_WVpl[d]);
}

// Vcat[h][f][2048+c] = E[h*64+c][f]  (smem transpose, 64x64 tiles)
__global__ void et_kernel()
{
    __shared__ __half sh[64 * 66], sl[64 * 66];
    const int h = blockIdx.x;
    const int f0 = blockIdx.y * 64;
#pragma unroll
    for (int t = 0; t < 16; t++) {
        int idx = threadIdx.x + t * 256;
        int c = idx >> 6, f = idx & 63;
        sh[c * 66 + f] = g_Eh[(size_t)(h * 64 + c) * FDN + f0 + f];
        sl[c * 66 + f] = g_El[(size_t)(h * 64 + c) * FDN + f0 + f];
    }
    __syncthreads();
#pragma unroll
    for (int t = 0; t < 16; t++) {
        int idx = threadIdx.x + t * 256;
        int f = idx >> 6, c = idx & 63;
        size_t o = ((size_t)h * FDN + f0 + f) * KC + FUN + c;
        g_Vh[o] = sh[c * 66 + f];
        g_Vl[o] = sl[c * 66 + f];
    }
}

__global__ void bias_v_kernel(const float* __restrict__ W_V,
                              const float* __restrict__ up_b_dec)
{
    int hk = blockIdx.x * blockDim.x + threadIdx.x;
    if (hk >= HN * DHN) return;
    int h = hk >> 6, k = hk & 63;
    const float* base = W_V + (size_t)h * DN * DHN + k;
    float s = 0.f;
    for (int m = 0; m < DN; m++) s = fmaf(base[(size_t)m * DHN], up_b_dec[m], s);
    g_v[hk] = s;
}

__global__ void bias_C_kernel(const float* __restrict__ W_O)
{
    int d = blockIdx.x * blockDim.x + threadIdx.x;
    if (d >= DN) return;
    float s = 0.f;
    for (int hk = 0; hk < HN * DHN; hk++)
        s = fmaf(g_v[hk], W_O[(size_t)hk * DN + d], s);
    g_C[d] = s;
}

__global__ void bias_g_kernel(const float* __restrict__ enc_W,
                              const float* __restrict__ enc_b,
                              const float* __restrict__ b_dec)
{
    int w = (blockIdx.x * blockDim.x + threadIdx.x) >> 5;
    int lane = threadIdx.x & 31;
    if (w >= FDN) return;
    const float* row = enc_W + (size_t)w * DN;
    float sg = 0.f, sb = 0.f;
    for (int d = lane; d < DN; d += 32) {
        float r = row[d];
        sg = fmaf(r, g_C[d], sg);
        sb = fmaf(r, b_dec[d], sb);
    }
#pragma unroll
    for (int o = 16; o; o >>= 1) {
        sg += __shfl_xor_sync(0xffffffffu, sg, o);
        sb += __shfl_xor_sync(0xffffffffu, sb, o);
    }
    if (lane == 0) { g_gvec[w] = sg; g_bias0[w] = enc_b[w] - sb; }
}

// --------------------------- launch ----------------------------------------
static constexpr int SMB128 = (2 * 128 * STRD + 2 * 128 * STRD) * 2 * 2; // 81920
static constexpr int SMB64  = (2 * 128 * STRD + 2 * 64 * STRD) * 2 * 2;  // 61440
static constexpr int SMFIN  = (1 * 128 * STRD + 2 * 128 * STRD) * 2 * 2; // 61440

template <typename T>
static const __half* dsym(T& sym) {
    void* p = nullptr;
    cudaGetSymbolAddress(&p, sym);
    return (const __half*)p;
}

extern "C" void kernel_launch(void* const* d_in, const int* in_sizes, int n_in,
                              void* d_out, int out_size)
{
    (void)in_sizes; (void)n_in; (void)out_size;
    const float* resid    = (const float*)d_in[0];
    const float* ln       = (const float*)d_in[1];
    const float* probs    = (const float*)d_in[2];
    const float* W_O      = (const float*)d_in[3];
    const float* W_V      = (const float*)d_in[4];
    const float* enc_W    = (const float*)d_in[5];
    const float* enc_b    = (const float*)d_in[6];
    const float* b_dec    = (const float*)d_in[7];
    const float* up_dec_W = (const float*)d_in[8];
    const float* up_b_dec = (const float*)d_in[9];
    const float* pruned   = (const float*)d_in[10];
    const int*   cmask    = (const int*)d_in[11];
    float* out = (float*)d_out;

    const __half *pEh = dsym(g_Eh), *pEl = dsym(g_El);
    const __half *pPh = dsym(g_Ph), *pPl = dsym(g_Pl);
    const __half *pT2h = dsym(g_t2h), *pT2l = dsym(g_t2l);
    const __half *pVh = dsym(g_Vh), *pVl = dsym(g_Vl);
    const __half *pRh = dsym(g_Rh), *pRl = dsym(g_Rl);
    const __half *pAch = dsym(g_acth), *pAcl = dsym(g_actl);
    const __half *pUph = dsym(g_uph), *pUpl = dsym(g_upl);
    const __half *pPrh = dsym(g_prh), *pPrl = dsym(g_prl);
    const __half *pWOh = dsym(g_WOh), *pWOl = dsym(g_WOl);
    const __half *pEWh = dsym(g_eWh), *pEWl = dsym(g_eWl);
    const __half *pWVph = dsym(g_WVph), *pWVpl = dsym(g_WVpl);
    const __half *pWVbh = dsym(g_WVbh), *pWVbl = dsym(g_WVbl);
    const __half *pUdh = dsym(g_udh), *pUdl = dsym(g_udl);

    cudaFuncSetAttribute((const void*)mma_gemm<128,0,0,false,2>,
                         cudaFuncAttributeMaxDynamicSharedMemorySize, SMB128);
    cudaFuncSetAttribute((const void*)mma_gemm<128,0,1,false,2>,
                         cudaFuncAttributeMaxDynamicSharedMemorySize, SMB128);
    cudaFuncSetAttribute((const void*)mma_gemm<64,0,1,false,4>,
                         cudaFuncAttributeMaxDynamicSharedMemorySize, SMB64);
    cudaFuncSetAttribute((const void*)mma_gemm<128,1,1,true,2>,
                         cudaFuncAttributeMaxDynamicSharedMemorySize, SMB128);
    cudaFuncSetAttribute((const void*)final_kernel,
                         cudaFuncAttributeMaxDynamicSharedMemorySize, SMFIN);

    // input splits + elementwise prep
    prep_kernel<<<BSN, 256>>>(resid, ln, pruned);
    split_arr<<<(DN*DN + 255)/256, 256>>>(W_O, (__half*)pWOh, (__half*)pWOl, DN*DN);
    split_arr<<<(FDN*DN + 255)/256, 256>>>(enc_W, (__half*)pEWh, (__half*)pEWl, FDN*DN);
    split_arr<<<(DN*DN + 255)/256, 256>>>(W_V, (__half*)pWVbh, (__half*)pWVbl, DN*DN);
    split_arr<<<(DN*FUN + 255)/256, 256>>>(up_dec_W, (__half*)pUdh, (__half*)pUdl, DN*FUN);
    split_arr<<<(4*HN*256*256 + 255)/256, 256>>>(probs, (__half*)pPrh, (__half*)pPrl, 4*HN*256*256);
    split_wvp<<<(DN*DN + 255)/256, 256>>>(W_V);

    // rank-1 bias chain (fp32)
    bias_v_kernel<<<3, 256>>>(W_V, up_b_dec);
    bias_C_kernel<<<3, 256>>>(W_O);
    bias_g_kernel<<<FDN * 32 / 256, 256>>>(enc_W, enc_b, b_dec);

    // E_flat[768,2048] = W_O_flat @ enc_W^T
    mma_gemm<128,0,0,false,2><<<dim3(16,6,1), 256, SMB128>>>(
        pWOh, pWOl, DN, 0, 0,
        pEWh, pEWl, DN, 0, 0,
        (__half*)pEh, (__half*)pEl, FDN, 0, 0,
        DN, 1, nullptr, 0);

    // P_flat[768,2048] = W_Vpack @ up_dec_W
    mma_gemm<128,0,1,false,2><<<dim3(16,6,1), 256, SMB128>>>(
        pWVph, pWVpl, DN, 0, 0,
        pUdh, pUdl, FUN, 0, 0,
        (__half*)pPh, (__half*)pPl, FUN, 0, 0,
        DN, 1, nullptr, 0);

    // Vcat[...][2048..2111] = E^T
    et_kernel<<<dim3(HN, FDN/64), 256>>>();

    // t2[h] = act_ln @ W_V[h] : M=1024,N=64,K=768
    mma_gemm<64,0,1,false,4><<<dim3(1,8,HN), 256, SMB64>>>(
        pAch, pAcl, DN, 0, 0,
        pWVbh, pWVbl, DHN, (long)DN*DHN, 0,
        (__half*)pT2h, (__half*)pT2l, DHN, (long)BSN*DHN, 0,
        DN, 1, nullptr, 0);

    // Vcat[...][0..2047] = mask .* (E[h]^T @ P[h]) : M=2048,N=2048,K=64
    mma_gemm<128,1,1,true,2><<<dim3(16,16,HN), 256, SMB128>>>(
        pEh, pEl, FDN, (long)DHN*FDN, 0,
        pPh, pPl, FUN, (long)DHN*FUN, 0,
        (__half*)pVh, (__half*)pVl, KC, (long)FDN*KC, 0,
        DHN, 1, cmask, FUN);

    // Rcat[...][2048..2111] = S1 = probs @ t2 : M=256,N=64,K=256
    mma_gemm<64,0,1,false,4><<<dim3(1,2,4*HN), 256, SMB64>>>(
        pPrh, pPrl, 256, (long)HN*256*256, (long)256*256,
        pT2h, pT2l, DHN, (long)256*DHN, (long)BSN*DHN,
        (__half*)pRh + FUN, (__half*)pRl + FUN, KC, (long)HN*256*KC, (long)256*KC,
        256, HN, nullptr, 0);

    // Rcat[...][0..2047] = R = probs @ up_ln : M=256,N=2048,K=256
    mma_gemm<128,0,1,false,2><<<dim3(16,2,4*HN), 256, SMB128>>>(
        pPrh, pPrl, 256, (long)HN*256*256, (long)256*256,
        pUph, pUpl, FUN, (long)256*FUN, 0,
        (__half*)pRh, (__half*)pRl, KC, (long)HN*256*KC, (long)256*KC,
        256, HN, nullptr, 0);

    // out = sum_h Rcat_hi @ (Vcat_hi + Vcat_lo/2048)^T + bias
    final_kernel<<<dim3(16,2,4), 256, SMFIN>>>(out);
}

// round 17
// speedup vs baseline: 3.3300x; 1.0718x over previous
#include <cuda_runtime.h>
#include <cuda_fp16.h>
#include <cstdint>
#include <cstddef>

// ---------------------------------------------------------------------------
// SCAEAttention, rank-64 factorization, legacy mma.sync m16n8k16 fp16.
// hh pass: f32-accum HMMA. ml (correction) passes: f16-accum HMMA (2x rate
// if the die supports double-rate fp16-accum; correction is /2048 so f16
// accumulation error is negligible).
// Upstream GEMMs: 3-pass hi/lo split; R/S1: 2-pass; final: 2-pass.
// Fragment loads via ldmatrix.m8n8 (LDSM).
//
//  E[hk,f]    = W_O_flat @ enc_W^T                    (768,2048,768)
//  P[hk,u]    = W_Vpack @ up_dec_W                    (768,2048,768)
//  virtual[h] = mask .* (E[h]^T @ P[h])               (2048,2048,64)x12
//  t2[h]      = act_ln @ W_V[h]                       (1024,64,768)x12
//  S1[b,h]    = probs[b,h] @ t2[h,b-rows]             (256,64,256)x48
//  R[b,h]     = probs[b,h] @ up_ln[b]                 (256,2048,256)x48
//  Rcat = [R | S1] (K=2112), Vcat = [virtual | E^T]
//  out[b,q,f] = sum_h Rcat[b,h] @ Vcat[h]^T + bias0 + inv*g
// ---------------------------------------------------------------------------

#define HN 12
#define DHN 64
#define DN 768
#define FDN 2048
#define FUN 2048
#define BSN 1024
#define KC 2112            // FUN + DHN

#define LO_SCALE 2048.0f
#define LO_INV   (1.0f / 2048.0f)
#define STRD 40            // halves per smem row (32 + 8 pad); 80B stride

// persistent fp16 hi/lo planes
__device__ __half g_Eh[DN * FDN],            g_El[DN * FDN];
__device__ __half g_Ph[DN * FUN],            g_Pl[DN * FUN];
__device__ __half g_t2h[HN * BSN * DHN],     g_t2l[HN * BSN * DHN];
__device__ __half g_Vh[(size_t)HN * FDN * KC], g_Vl[(size_t)HN * FDN * KC];
__device__ __half g_Rh[(size_t)4 * HN * 256 * KC], g_Rl[(size_t)4 * HN * 256 * KC];
__device__ __half g_acth[BSN * DN],          g_actl[BSN * DN];
__device__ __half g_uph[BSN * FUN],          g_upl[BSN * FUN];
__device__ __half g_prh[4 * HN * 256 * 256], g_prl[4 * HN * 256 * 256];
__device__ __half g_WOh[DN * DN],            g_WOl[DN * DN];
__device__ __half g_eWh[FDN * DN],           g_eWl[FDN * DN];
__device__ __half g_WVph[DN * DN],           g_WVpl[DN * DN];  // [hk][i]
__device__ __half g_WVbh[DN * DN],           g_WVbl[DN * DN];  // [h][i][kdh]
__device__ __half g_udh[DN * FUN],           g_udl[DN * FUN];
__device__ float g_inv[BSN];
__device__ float g_v[HN * DHN];
__device__ float g_C[DN];
__device__ float g_gvec[FDN];
__device__ float g_bias0[FDN];

// ------------------------------- helpers -----------------------------------
__device__ __forceinline__ void mma_f16(float (&c)[4], const uint32_t (&a)[4],
                                        const uint32_t (&b)[2])
{
    asm volatile(
        "mma.sync.aligned.m16n8k16.row.col.f32.f16.f16.f32 "
        "{%0,%1,%2,%3}, {%4,%5,%6,%7}, {%8,%9}, {%0,%1,%2,%3};"
        : "+f"(c[0]), "+f"(c[1]), "+f"(c[2]), "+f"(c[3])
        : "r"(a[0]), "r"(a[1]), "r"(a[2]), "r"(a[3]), "r"(b[0]), "r"(b[1]));
}

// fp16-accumulator variant: d/c are 2 x .f16x2 regs
__device__ __forceinline__ void mma_f16h(uint32_t (&c)[2], const uint32_t (&a)[4],
                                         const uint32_t (&b)[2])
{
    asm volatile(
        "mma.sync.aligned.m16n8k16.row.col.f16.f16.f16.f16 "
        "{%0,%1}, {%2,%3,%4,%5}, {%6,%7}, {%0,%1};"
        : "+r"(c[0]), "+r"(c[1])
        : "r"(a[0]), "r"(a[1]), "r"(a[2]), "r"(a[3]), "r"(b[0]), "r"(b[1]));
}

__device__ __forceinline__ void ldsm_x4(uint32_t (&r)[4], uint32_t addr)
{
    asm volatile("ldmatrix.sync.aligned.m8n8.x4.shared.b16 {%0,%1,%2,%3}, [%4];"
                 : "=r"(r[0]), "=r"(r[1]), "=r"(r[2]), "=r"(r[3]) : "r"(addr));
}

__device__ __forceinline__ uint32_t smem_u32(const void* p)
{
    uint32_t a;
    asm("{ .reg .u64 t; cvta.to.shared.u64 t, %1; cvt.u32.u64 %0, t; }"
        : "=r"(a) : "l"(p));
    return a;
}

__device__ __forceinline__ void split_one(float v, __half& h, __half& l)
{
    h = __float2half_rn(v);
    l = __float2half_rn((v - __half2float(h)) * LO_SCALE);
}

__device__ __forceinline__ void split_pack(float x, float y,
                                           uint32_t& hi2, uint32_t& lo2)
{
    __half hx, lx, hy, ly;
    split_one(x, hx, lx);
    split_one(y, hy, ly);
    hi2 = ((uint32_t)__half_as_ushort(hy) << 16) | __half_as_ushort(hx);
    lo2 = ((uint32_t)__half_as_ushort(ly) << 16) | __half_as_ushort(lx);
}

// ------------------ staging: plane gmem -> regs -> smem --------------------
// MODE 0: X[m*ld + k] (k-fast); MODE 1: X[k*ld + m] (m-fast)
template <int ROWS, int MODE, bool LO>
__device__ __forceinline__ void ld_tile_h(
    const __half* __restrict__ Xh, const __half* __restrict__ Xl,
    int ld, int k0, int row0, uint32_t* rh, uint32_t* rl)
{
    constexpr int IT = ROWS / 16;
#pragma unroll
    for (int t = 0; t < IT; t++) {
        int p = threadIdx.x + t * 256;
        size_t idx;
        if (MODE == 0) {
            int m = p >> 4, kp = (p & 15) * 2;
            idx = (size_t)(row0 + m) * ld + k0 + kp;
        } else {
            constexpr int MP = ROWS / 2;
            int k = p / MP, m2 = (p % MP) * 2;
            idx = (size_t)(k0 + k) * ld + row0 + m2;
        }
        rh[t] = *(const uint32_t*)(Xh + idx);
        if (LO) rl[t] = *(const uint32_t*)(Xl + idx);
    }
}

template <int ROWS, int MODE, bool LO>
__device__ __forceinline__ void st_tile_h(const uint32_t* rh, const uint32_t* rl,
                                          __half* hp, __half* lp)
{
    constexpr int IT = ROWS / 16;
#pragma unroll
    for (int t = 0; t < IT; t++) {
        int p = threadIdx.x + t * 256;
        if (MODE == 0) {
            int m = p >> 4, kp = (p & 15) * 2;
            *(uint32_t*)(hp + m * STRD + kp) = rh[t];
            if (LO) *(uint32_t*)(lp + m * STRD + kp) = rl[t];
        } else {
            constexpr int MP = ROWS / 2;
            int k = p / MP, m2 = (p % MP) * 2;
            hp[m2 * STRD + k]       = __ushort_as_half((unsigned short)(rh[t] & 0xffff));
            hp[(m2 + 1) * STRD + k] = __ushort_as_half((unsigned short)(rh[t] >> 16));
            if (LO) {
                lp[m2 * STRD + k]       = __ushort_as_half((unsigned short)(rl[t] & 0xffff));
                lp[(m2 + 1) * STRD + k] = __ushort_as_half((unsigned short)(rl[t] >> 16));
            }
        }
    }
}

// --------------------------- fp16 split GEMM stage -------------------------
// PASSES==3: hh += Ah*Bh (f32), ml += Ah*Bl + Al*Bh (f16 accum)
// PASSES==2: hh += Ah*Bh (f32), ml += Ah*Bl (f16 accum); A hi only staged
template <int BN, int AMODE, int BMODE, int WM, int PASSES>
__device__ __forceinline__ void mma_stage(
    const __half* __restrict__ Agh, const __half* __restrict__ Agl, int lda,
    const __half* __restrict__ Bgh, const __half* __restrict__ Bgl, int ldb,
    int K, int tileM, int tileN,
    float (&hh)[8 / WM][BN * WM / 64][4],
    uint32_t (&ml)[8 / WM][BN * WM / 64][2],
    __half* sm)
{
    constexpr int WN = 8 / WM;
    constexpr int MT = 8 / WM;
    constexpr int NT = BN * WM / 64;
    constexpr bool ALO = (PASSES == 3);
    constexpr int APLANES = ALO ? 2 : 1;
    constexpr int APL = 128 * STRD;
    constexpr int BPL = BN * STRD;
    constexpr int BUF = APLANES * APL + 2 * BPL;   // halves per buffer

    const int lane = threadIdx.x & 31, warp = threadIdx.x >> 5;
    const int wm = (warp % WM) * (128 / WM);
    const int wn = (warp / WM) * (BN / WN);

    const uint32_t smu = smem_u32(sm);

    // ldmatrix lane-dependent byte offsets (within a plane)
    uint32_t aOff[MT], bOff[NT / 2];
#pragma unroll
    for (int i = 0; i < MT; i++)
        aOff[i] = (uint32_t)(((wm + i * 16 + (lane & 15)) * STRD
                              + ((lane >> 4) & 1) * 8) * 2);
#pragma unroll
    for (int jp = 0; jp < NT / 2; jp++)
        bOff[jp] = (uint32_t)(((wn + (jp * 2 + ((lane >> 4) & 1)) * 8 + (lane & 7)) * STRD
                               + ((lane >> 3) & 1) * 8) * 2);

    uint32_t raH[8], raL[ALO ? 8 : 1], rbH[BN / 16], rbL[BN / 16];

    auto stor = [&](int buf) {
        __half* base = sm + buf * BUF;
        st_tile_h<128, AMODE, ALO>(raH, raL, base, base + APL);
        st_tile_h<BN, BMODE, true>(rbH, rbL, base + APLANES * APL,
                                   base + APLANES * APL + BPL);
    };
    auto comp = [&](int buf) {
        const uint32_t aBaseH = smu + (uint32_t)(buf * BUF) * 2;
        const uint32_t aBaseL = aBaseH + APL * 2;
        const uint32_t bBaseH = aBaseH + APLANES * APL * 2;
        const uint32_t bBaseL = bBaseH + BPL * 2;
#pragma unroll
        for (int ks = 0; ks < 32; ks += 16) {
            uint32_t afh[MT][4], afl[ALO ? MT : 1][4], bfh[NT][2], bfl[NT][2];
#pragma unroll
            for (int i = 0; i < MT; i++)
                ldsm_x4(afh[i], aBaseH + aOff[i] + ks * 2);
            if (ALO) {
#pragma unroll
                for (int i = 0; i < MT; i++)
                    ldsm_x4(afl[i], aBaseL + aOff[i] + ks * 2);
            }
#pragma unroll
            for (int jp = 0; jp < NT / 2; jp++) {
                uint32_t t[4];
                ldsm_x4(t, bBaseH + bOff[jp] + ks * 2);
                bfh[jp * 2][0] = t[0]; bfh[jp * 2][1] = t[1];
                bfh[jp * 2 + 1][0] = t[2]; bfh[jp * 2 + 1][1] = t[3];
                ldsm_x4(t, bBaseL + bOff[jp] + ks * 2);
                bfl[jp * 2][0] = t[0]; bfl[jp * 2][1] = t[1];
                bfl[jp * 2 + 1][0] = t[2]; bfl[jp * 2 + 1][1] = t[3];
            }
#pragma unroll
            for (int i = 0; i < MT; i++)
#pragma unroll
                for (int j = 0; j < NT; j++) {
                    mma_f16(hh[i][j], afh[i], bfh[j]);
                    mma_f16h(ml[i][j], afh[i], bfl[j]);
                    if (ALO) mma_f16h(ml[i][j], afl[i], bfh[j]);
                }
        }
    };

    const int niter = K / 32;
    ld_tile_h<128, AMODE, ALO>(Agh, Agl, lda, 0, tileM, raH, raL);
    ld_tile_h<BN, BMODE, true>(Bgh, Bgl, ldb, 0, tileN, rbH, rbL);
    stor(0);
    __syncthreads();
    for (int it = 0; it < niter; it++) {
        if (it + 1 < niter) {
            ld_tile_h<128, AMODE, ALO>(Agh, Agl, lda, (it + 1) * 32, tileM, raH, raL);
            ld_tile_h<BN, BMODE, true>(Bgh, Bgl, ldb, (it + 1) * 32, tileN, rbH, rbL);
        }
        comp(it & 1);
        if (it + 1 < niter) stor((it + 1) & 1);
        __syncthreads();
    }
}

// --------------------------- generic mma GEMM ------------------------------
template <int BN, int AMODE, int BMODE, bool MASK_, int WM, int PASSES, bool WRLO>
__global__ void __launch_bounds__(256, 1) mma_gemm(
    const __half* __restrict__ Ah, const __half* __restrict__ Al,
    int lda, long sAo, long sAi,
    const __half* __restrict__ Bh, const __half* __restrict__ Bl,
    int ldb, long sBo, long sBi,
    __half* __restrict__ Ch, __half* __restrict__ Cl,
    int ldc, long sCo, long sCi,
    int K, int bsplit,
    const int* __restrict__ mask, int mld)
{
    constexpr int MT = 8 / WM;
    constexpr int NT = BN * WM / 64;
    extern __shared__ __half sm[];

    const int bz = blockIdx.z;
    const int bo = bz / bsplit, bi = bz - bo * bsplit;
    Ah += bo * sAo + bi * sAi;  Al += bo * sAo + bi * sAi;
    Bh += bo * sBo + bi * sBi;  Bl += bo * sBo + bi * sBi;
    Ch += bo * sCo + bi * sCi;  Cl += bo * sCo + bi * sCi;
    const int tileM = blockIdx.y * 128;
    const int tileN = blockIdx.x * BN;

    float hh[MT][NT][4] = {};
    uint32_t ml[MT][NT][2] = {};
    mma_stage<BN, AMODE, BMODE, WM, PASSES>(Ah, Al, lda, Bh, Bl, ldb,
                                            K, tileM, tileN, hh, ml, sm);

    const int lane = threadIdx.x & 31, warp = threadIdx.x >> 5;
    const int g = lane >> 2, tc = lane & 3;
    const int wm = (warp % WM) * (128 / WM);
    const int wn = (warp / WM) * (BN / (8 / WM));

#pragma unroll
    for (int i = 0; i < MT; i++) {
        int m0 = tileM + wm + i * 16 + g;
#pragma unroll
        for (int j = 0; j < NT; j++) {
            int n0 = tileN + wn + j * 8 + 2 * tc;
            float2 m01 = __half22float2(*(__half2*)&ml[i][j][0]);
            float2 m23 = __half22float2(*(__half2*)&ml[i][j][1]);
            float v0 = hh[i][j][0] + m01.x * LO_INV;
            float v1 = hh[i][j][1] + m01.y * LO_INV;
            float v2 = hh[i][j][2] + m23.x * LO_INV;
            float v3 = hh[i][j][3] + m23.y * LO_INV;
            if (MASK_) {
                v0 *= (float)mask[(size_t)m0 * mld + n0];
                v1 *= (float)mask[(size_t)m0 * mld + n0 + 1];
                v2 *= (float)mask[(size_t)(m0 + 8) * mld + n0];
                v3 *= (float)mask[(size_t)(m0 + 8) * mld + n0 + 1];
            }
            uint32_t h2, l2;
            split_pack(v0, v1, h2, l2);
            *(uint32_t*)(Ch + (size_t)m0 * ldc + n0) = h2;
            if (WRLO) *(uint32_t*)(Cl + (size_t)m0 * ldc + n0) = l2;
            split_pack(v2, v3, h2, l2);
            *(uint32_t*)(Ch + (size_t)(m0 + 8) * ldc + n0) = h2;
            if (WRLO) *(uint32_t*)(Cl + (size_t)(m0 + 8) * ldc + n0) = l2;
        }
    }
}

// --------------------------- final fused kernel (2-pass) -------------------
// out[b,q,f] = sum_h Rcat_hi[b,h] @ (Vcat_hi + Vcat_lo/2048)[h]^T + bias
__global__ void __launch_bounds__(256, 1) final_kernel(float* __restrict__ out)
{
    constexpr int WM = 2, MT = 4, NT = 4;
    extern __shared__ __half sm[];

    const int b = blockIdx.z;
    const int tileM = blockIdx.y * 128;
    const int tileN = blockIdx.x * 128;

    float hh[MT][NT][4] = {};
    uint32_t ml[MT][NT][2] = {};

    for (int h = 0; h < HN; ++h) {
        size_t ao = (size_t)(b * HN + h) * 256 * KC;
        size_t bo = (size_t)h * FDN * KC;
        mma_stage<128, 0, 0, WM, 2>(g_Rh + ao, g_Rh + ao, KC,
                                    g_Vh + bo, g_Vl + bo, KC,
                                    KC, tileM, tileN, hh, ml, sm);
    }

    const int lane = threadIdx.x & 31, warp = threadIdx.x >> 5;
    const int g = lane >> 2, tc = lane & 3;
    const int wm = (warp % WM) * 64;
    const int wn = (warp / WM) * 32;

#pragma unroll
    for (int i = 0; i < MT; i++) {
        int q0 = tileM + wm + i * 16 + g;
        float inv0 = g_inv[b * 256 + q0];
        float inv1 = g_inv[b * 256 + q0 + 8];
#pragma unroll
        for (int j = 0; j < NT; j++) {
            int f0 = tileN + wn + j * 8 + 2 * tc;
            float2 m01 = __half22float2(*(__half2*)&ml[i][j][0]);
            float2 m23 = __half22float2(*(__half2*)&ml[i][j][1]);
            float bA = g_bias0[f0], bB = g_bias0[f0 + 1];
            float gA = g_gvec[f0],  gB = g_gvec[f0 + 1];
            out[((size_t)b * 256 + q0) * FDN + f0] =
                hh[i][j][0] + m01.x * LO_INV + bA + inv0 * gA;
            out[((size_t)b * 256 + q0) * FDN + f0 + 1] =
                hh[i][j][1] + m01.y * LO_INV + bB + inv0 * gB;
            out[((size_t)b * 256 + q0 + 8) * FDN + f0] =
                hh[i][j][2] + m23.x * LO_INV + bA + inv1 * gA;
            out[((size_t)b * 256 + q0 + 8) * FDN + f0 + 1] =
                hh[i][j][3] + m23.y * LO_INV + bB + inv1 * gB;
        }
    }
}

// --------------------------- small kernels ---------------------------------
__global__ void prep_kernel(const float* __restrict__ resid,
                            const float* __restrict__ ln,
                            const float* __restrict__ pruned)
{
    int row = blockIdx.x;
    float inv = 1.0f / ln[row];
    if (threadIdx.x == 0) g_inv[row] = inv;
    for (int d = threadIdx.x; d < DN; d += blockDim.x) {
        float v = resid[(size_t)row * DN + d] * inv;
        split_one(v, g_acth[(size_t)row * DN + d], g_actl[(size_t)row * DN + d]);
    }
    for (int u = threadIdx.x; u < FUN; u += blockDim.x) {
        float v = pruned[(size_t)row * FUN + u] * inv;
        split_one(v, g_uph[(size_t)row * FUN + u], g_upl[(size_t)row * FUN + u]);
    }
}

__global__ void split_arr(const float* __restrict__ src,
                          __half* __restrict__ dh, __half* __restrict__ dl, int n)
{
    int i = blockIdx.x * blockDim.x + threadIdx.x;
    if (i < n) split_one(src[i], dh[i], dl[i]);
}

// W_V [h][i][k] -> packed [hk][i]
__global__ void split_wvp(const float* __restrict__ W_V)
{
    int d = blockIdx.x * blockDim.x + threadIdx.x;
    if (d >= DN * DN) return;
    int hk = d / DN, ii = d - hk * DN;
    float v = W_V[(size_t)(hk >> 6) * (DN * DHN) + (size_t)ii * DHN + (hk & 63)];
    split_one(v, g_WVph[d], g_WVpl[d]);
}

// Vcat[h][f][2048+c] = E[h*64+c][f]  (smem transpose, 64x64 tiles)
__global__ void et_kernel()
{
    __shared__ __half sh[64 * 66], sl[64 * 66];
    const int h = blockIdx.x;
    const int f0 = blockIdx.y * 64;
#pragma unroll
    for (int t = 0; t < 16; t++) {
        int idx = threadIdx.x + t * 256;
        int c = idx >> 6, f = idx & 63;
        sh[c * 66 + f] = g_Eh[(size_t)(h * 64 + c) * FDN + f0 + f];
        sl[c * 66 + f] = g_El[(size_t)(h * 64 + c) * FDN + f0 + f];
    }
    __syncthreads();
#pragma unroll
    for (int t = 0; t < 16; t++) {
        int idx = threadIdx.x + t * 256;
        int f = idx >> 6, c = idx & 63;
        size_t o = ((size_t)h * FDN + f0 + f) * KC + FUN + c;
        g_Vh[o] = sh[c * 66 + f];
        g_Vl[o] = sl[c * 66 + f];
    }
}

__global__ void bias_v_kernel(const float* __restrict__ W_V,
                              const float* __restrict__ up_b_dec)
{
    int hk = blockIdx.x * blockDim.x + threadIdx.x;
    if (hk >= HN * DHN) return;
    int h = hk >> 6, k = hk & 63;
    const float* base = W_V + (size_t)h * DN * DHN + k;
    float s = 0.f;
    for (int m = 0; m < DN; m++) s = fmaf(base[(size_t)m * DHN], up_b_dec[m], s);
    g_v[hk] = s;
}

__global__ void bias_C_kernel(const float* __restrict__ W_O)
{
    int d = blockIdx.x * blockDim.x + threadIdx.x;
    if (d >= DN) return;
    float s = 0.f;
    for (int hk = 0; hk < HN * DHN; hk++)
        s = fmaf(g_v[hk], W_O[(size_t)hk * DN + d], s);
    g_C[d] = s;
}

__global__ void bias_g_kernel(const float* __restrict__ enc_W,
                              const float* __restrict__ enc_b,
                              const float* __restrict__ b_dec)
{
    int w = (blockIdx.x * blockDim.x + threadIdx.x) >> 5;
    int lane = threadIdx.x & 31;
    if (w >= FDN) return;
    const float* row = enc_W + (size_t)w * DN;
    float sg = 0.f, sb = 0.f;
    for (int d = lane; d < DN; d += 32) {
        float r = row[d];
        sg = fmaf(r, g_C[d], sg);
        sb = fmaf(r, b_dec[d], sb);
    }
#pragma unroll
    for (int o = 16; o; o >>= 1) {
        sg += __shfl_xor_sync(0xffffffffu, sg, o);
        sb += __shfl_xor_sync(0xffffffffu, sb, o);
    }
    if (lane == 0) { g_gvec[w] = sg; g_bias0[w] = enc_b[w] - sb; }
}

// --------------------------- launch ----------------------------------------
static constexpr int smb(int BN, int PASSES) {
    return ((PASSES == 3 ? 2 : 1) * 128 * STRD + 2 * BN * STRD) * 2 * 2;
}

template <typename T>
static const __half* dsym(T& sym) {
    void* p = nullptr;
    cudaGetSymbolAddress(&p, sym);
    return (const __half*)p;
}

extern "C" void kernel_launch(void* const* d_in, const int* in_sizes, int n_in,
                              void* d_out, int out_size)
{
    (void)in_sizes; (void)n_in; (void)out_size;
    const float* resid    = (const float*)d_in[0];
    const float* ln       = (const float*)d_in[1];
    const float* probs    = (const float*)d_in[2];
    const float* W_O      = (const float*)d_in[3];
    const float* W_V      = (const float*)d_in[4];
    const float* enc_W    = (const float*)d_in[5];
    const float* enc_b    = (const float*)d_in[6];
    const float* b_dec    = (const float*)d_in[7];
    const float* up_dec_W = (const float*)d_in[8];
    const float* up_b_dec = (const float*)d_in[9];
    const float* pruned   = (const float*)d_in[10];
    const int*   cmask    = (const int*)d_in[11];
    float* out = (float*)d_out;

    const __half *pEh = dsym(g_Eh), *pEl = dsym(g_El);
    const __half *pPh = dsym(g_Ph), *pPl = dsym(g_Pl);
    const __half *pT2h = dsym(g_t2h), *pT2l = dsym(g_t2l);
    const __half *pVh = dsym(g_Vh), *pVl = dsym(g_Vl);
    const __half *pRh = dsym(g_Rh), *pRl = dsym(g_Rl);
    const __half *pAch = dsym(g_acth), *pAcl = dsym(g_actl);
    const __half *pUph = dsym(g_uph), *pUpl = dsym(g_upl);
    const __half *pPrh = dsym(g_prh), *pPrl = dsym(g_prl);
    const __half *pWOh = dsym(g_WOh), *pWOl = dsym(g_WOl);
    const __half *pEWh = dsym(g_eWh), *pEWl = dsym(g_eWl);
    const __half *pWVph = dsym(g_WVph), *pWVpl = dsym(g_WVpl);
    const __half *pWVbh = dsym(g_WVbh), *pWVbl = dsym(g_WVbl);
    const __half *pUdh = dsym(g_udh), *pUdl = dsym(g_udl);

    cudaFuncSetAttribute((const void*)mma_gemm<128,0,0,false,2,3,true>,
                         cudaFuncAttributeMaxDynamicSharedMemorySize, smb(128,3));
    cudaFuncSetAttribute((const void*)mma_gemm<128,0,1,false,2,3,true>,
                         cudaFuncAttributeMaxDynamicSharedMemorySize, smb(128,3));
    cudaFuncSetAttribute((const void*)mma_gemm<64,0,1,false,4,3,true>,
                         cudaFuncAttributeMaxDynamicSharedMemorySize, smb(64,3));
    cudaFuncSetAttribute((const void*)mma_gemm<128,1,1,true,2,3,true>,
                         cudaFuncAttributeMaxDynamicSharedMemorySize, smb(128,3));
    cudaFuncSetAttribute((const void*)mma_gemm<64,0,1,false,4,2,false>,
                         cudaFuncAttributeMaxDynamicSharedMemorySize, smb(64,2));
    cudaFuncSetAttribute((const void*)mma_gemm<128,0,1,false,2,2,false>,
                         cudaFuncAttributeMaxDynamicSharedMemorySize, smb(128,2));
    cudaFuncSetAttribute((const void*)final_kernel,
                         cudaFuncAttributeMaxDynamicSharedMemorySize, smb(128,2));

    // input splits + elementwise prep
    prep_kernel<<<BSN, 256>>>(resid, ln, pruned);
    split_arr<<<(DN*DN + 255)/256, 256>>>(W_O, (__half*)pWOh, (__half*)pWOl, DN*DN);
    split_arr<<<(FDN*DN + 255)/256, 256>>>(enc_W, (__half*)pEWh, (__half*)pEWl, FDN*DN);
    split_arr<<<(DN*DN + 255)/256, 256>>>(W_V, (__half*)pWVbh, (__half*)pWVbl, DN*DN);
    split_arr<<<(DN*FUN + 255)/256, 256>>>(up_dec_W, (__half*)pUdh, (__half*)pUdl, DN*FUN);
    split_arr<<<(4*HN*256*256 + 255)/256, 256>>>(probs, (__half*)pPrh, (__half*)pPrl, 4*HN*256*256);
    split_wvp<<<(DN*DN + 255)/256, 256>>>(W_V);

    // rank-1 bias chain (fp32)
    bias_v_kernel<<<3, 256>>>(W_V, up_b_dec);
    bias_C_kernel<<<3, 256>>>(W_O);
    bias_g_kernel<<<FDN * 32 / 256, 256>>>(enc_W, enc_b, b_dec);

    // E_flat[768,2048] = W_O_flat @ enc_W^T   (3-pass)
    mma_gemm<128,0,0,false,2,3,true><<<dim3(16,6,1), 256, smb(128,3)>>>(
        pWOh, pWOl, DN, 0, 0,
        pEWh, pEWl, DN, 0, 0,
        (__half*)pEh, (__half*)pEl, FDN, 0, 0,
        DN, 1, nullptr, 0);

    // P_flat[768,2048] = W_Vpack @ up_dec_W   (3-pass)
    mma_gemm<128,0,1,false,2,3,true><<<dim3(16,6,1), 256, smb(128,3)>>>(
        pWVph, pWVpl, DN, 0, 0,
        pUdh, pUdl, FUN, 0, 0,
        (__half*)pPh, (__half*)pPl, FUN, 0, 0,
        DN, 1, nullptr, 0);

    // Vcat[...][2048..2111] = E^T
    et_kernel<<<dim3(HN, FDN/64), 256>>>();

    // t2[h] = act_ln @ W_V[h] : M=1024,N=64,K=768   (3-pass)
    mma_gemm<64,0,1,false,4,3,true><<<dim3(1,8,HN), 256, smb(64,3)>>>(
        pAch, pAcl, DN, 0, 0,
        pWVbh, pWVbl, DHN, (long)DN*DHN, 0,
        (__half*)pT2h, (__half*)pT2l, DHN, (long)BSN*DHN, 0,
        DN, 1, nullptr, 0);

    // Vcat[...][0..2047] = mask .* (E[h]^T @ P[h]) : M=2048,N=2048,K=64  (3-pass)
    mma_gemm<128,1,1,true,2,3,true><<<dim3(16,16,HN), 256, smb(128,3)>>>(
        pEh, pEl, FDN, (long)DHN*FDN, 0,
        pPh, pPl, FUN, (long)DHN*FUN, 0,
        (__half*)pVh, (__half*)pVl, KC, (long)FDN*KC, 0,
        DHN, 1, cmask, FUN);

    // Rcat[...][2048..2111] = S1 = probs @ t2 : M=256,N=64,K=256   (2-pass, hi only)
    mma_gemm<64,0,1,false,4,2,false><<<dim3(1,2,4*HN), 256, smb(64,2)>>>(
        pPrh, pPrh, 256, (long)HN*256*256, (long)256*256,
        pT2h, pT2l, DHN, (long)256*DHN, (long)BSN*DHN,
        (__half*)pRh + FUN, (__half*)pRl + FUN, KC, (long)HN*256*KC, (long)256*KC,
        256, HN, nullptr, 0);

    // Rcat[...][0..2047] = R = probs @ up_ln : M=256,N=2048,K=256   (2-pass, hi only)
    mma_gemm<128,0,1,false,2,2,false><<<dim3(16,2,4*HN), 256, smb(128,2)>>>(
        pPrh, pPrh, 256, (long)HN*256*256, (long)256*256,
        pUph, pUpl, FUN, (long)256*FUN, 0,
        (__half*)pRh, (__half*)pRl, KC, (long)HN*256*KC, (long)256*KC,
        256, HN, nullptr, 0);

    // out = sum_h Rcat_hi @ (Vcat_hi + Vcat_lo/2048)^T + bias
    final_kernel<<<dim3(16,2,4), 256, smb(128,2)>>>(out);
}